// round 12
// baseline (speedup 1.0000x reference)
#include <cuda_runtime.h>
#include <cuda_bf16.h>
#include <math.h>
#include <stdint.h>

// ---------------------------------------------------------------------------
// Problem: x [16,48,207,512], 8 heads, d=64.  M = 158976 rows, K=N=512.
// ---------------------------------------------------------------------------
#define MB   16
#define TT   48
#define NV   207
#define FF   512
#define NHEAD 8
#define HD   64
#define MROWS (MB*TT*NV)          // 158976
#define SZ   ((size_t)MROWS * FF)

__device__ float g_scratch[6 * SZ];

// ---------------------------------------------------------------------------
// helpers
// ---------------------------------------------------------------------------
__device__ __forceinline__ void cp_async16(void* smem, const void* gmem) {
    unsigned s = (unsigned)__cvta_generic_to_shared(smem);
    asm volatile("cp.async.cg.shared.global [%0], [%1], 16;\n" :: "r"(s), "l"(gmem));
}
__device__ __forceinline__ void cp_commit() { asm volatile("cp.async.commit_group;\n" ::: "memory"); }
__device__ __forceinline__ void cp_wait0()  { asm volatile("cp.async.wait_group 0;\n" ::: "memory"); }

__device__ __forceinline__ void mma_bf16(float c[4], const uint32_t a[4], const uint32_t* b) {
    asm volatile(
        "mma.sync.aligned.m16n8k16.row.col.f32.bf16.bf16.f32 "
        "{%0,%1,%2,%3}, {%4,%5,%6,%7}, {%8,%9}, {%0,%1,%2,%3};\n"
        : "+f"(c[0]), "+f"(c[1]), "+f"(c[2]), "+f"(c[3])
        : "r"(a[0]), "r"(a[1]), "r"(a[2]), "r"(a[3]), "r"(b[0]), "r"(b[1]));
}
__device__ __forceinline__ void ldsm_x4(uint32_t r[4], uint32_t addr) {
    asm volatile("ldmatrix.sync.aligned.m8n8.x4.shared.b16 {%0,%1,%2,%3}, [%4];"
                 : "=r"(r[0]), "=r"(r[1]), "=r"(r[2]), "=r"(r[3]) : "r"(addr));
}

// ---------------------------------------------------------------------------
// bf16 HMMA GEMM: C = act(A[M,512] @ Bt^T + bias) (+resid)
//   CTA tile 64x128x64, 128 threads (4 warps in n), warp tile 64x32, ldmatrix,
//   2-stage cp.async pipeline, 4 CTAs/SM (measured-best config).
//   act: 0 bias->fp32 ; 1 bias+GELU->bf16 ; 2 bias+resid->fp32 ; 3 bias->bf16
// ---------------------------------------------------------------------------
#define BM 64
#define BN 128
#define BK 64
#define LDT 72
#define KDIM 512
#define KT (KDIM / BK)   // 8
#define A_BYTES (BM * LDT * 2)            // 9216
#define B_BYTES (BN * LDT * 2)            // 18432
#define GEMM_SMEM (2 * (A_BYTES + B_BYTES))   // 55296

__global__ __launch_bounds__(128, 4)
void gemm_bf16(const __nv_bfloat16* __restrict__ A,
               const __nv_bfloat16* __restrict__ Bt,
               const float* __restrict__ bias,
               const float* __restrict__ resid,
               void* __restrict__ C, int ldc, int act)
{
    extern __shared__ __align__(16) uint8_t dsm[];

    const int tid  = threadIdx.x;
    const int m0   = blockIdx.y * BM;
    const int n0   = blockIdx.x * BN;
    const int warp = tid >> 5;
    const int lane = tid & 31;
    const int wn   = warp * 32;
    const int g    = lane >> 2;
    const int t4   = lane & 3;

    uint8_t* As[2] = { dsm,                dsm + A_BYTES };
    uint8_t* Bs[2] = { dsm + 2 * A_BYTES,  dsm + 2 * A_BYTES + B_BYTES };
    const uint32_t sm_base = (uint32_t)__cvta_generic_to_shared(dsm);

    const int lr        = lane & 7;
    const int a_row_off = ((lane >> 3) & 1) * 8;
    const int a_col_off = (lane >> 4) * 8;
    const int b_row_off = (lane >> 4) * 8;
    const int b_col_off = ((lane >> 3) & 1) * 8;

    float c[4][4][4];
    #pragma unroll
    for (int i = 0; i < 4; i++)
        #pragma unroll
        for (int j = 0; j < 4; j++)
            #pragma unroll
            for (int r = 0; r < 4; r++) c[i][j][r] = 0.f;

    auto load_tiles = [&](int kt, int buf) {
        #pragma unroll
        for (int r = 0; r < 4; r++) {
            int ch  = tid + r * 128;
            int row = ch >> 3;
            int col = (ch & 7) * 8;
            cp_async16(As[buf] + row * (LDT * 2) + col * 2,
                       A + (size_t)(m0 + row) * KDIM + kt * BK + col);
        }
        #pragma unroll
        for (int r = 0; r < 8; r++) {
            int ch  = tid + r * 128;
            int row = ch >> 3;
            int col = (ch & 7) * 8;
            cp_async16(Bs[buf] + row * (LDT * 2) + col * 2,
                       Bt + (size_t)(n0 + row) * KDIM + kt * BK + col);
        }
    };

    load_tiles(0, 0);
    cp_commit();

    for (int kt = 0; kt < KT; kt++) {
        cp_wait0();
        __syncthreads();
        if (kt + 1 < KT) {
            load_tiles(kt + 1, (kt + 1) & 1);
            cp_commit();
        }
        const int buf = kt & 1;
        const uint32_t a_base = sm_base + buf * A_BYTES;
        const uint32_t b_base = sm_base + 2 * A_BYTES + buf * B_BYTES;

        #pragma unroll
        for (int kk = 0; kk < BK; kk += 16) {
            uint32_t af[4][4];
            #pragma unroll
            for (int i = 0; i < 4; i++)
                ldsm_x4(af[i], a_base +
                        ((i * 16 + lr + a_row_off) * LDT + kk + a_col_off) * 2);
            uint32_t bfr[2][4];
            #pragma unroll
            for (int jp = 0; jp < 2; jp++)
                ldsm_x4(bfr[jp], b_base +
                        ((wn + jp * 16 + lr + b_row_off) * LDT + kk + b_col_off) * 2);
            #pragma unroll
            for (int i = 0; i < 4; i++)
                #pragma unroll
                for (int j = 0; j < 4; j++)
                    mma_bf16(c[i][j], af[i], &bfr[j >> 1][(j & 1) * 2]);
        }
        // no trailing __syncthreads (2-stage rotation ordered by top barrier)
    }

    #pragma unroll
    for (int i = 0; i < 4; i++) {
        int row0 = m0 + i * 16 + g;
        int row1 = row0 + 8;
        #pragma unroll
        for (int j = 0; j < 4; j++) {
            int col = n0 + wn + j * 8 + 2 * t4;
            float b0 = bias[col], b1 = bias[col + 1];
            float v00 = c[i][j][0] + b0;
            float v01 = c[i][j][1] + b1;
            float v10 = c[i][j][2] + b0;
            float v11 = c[i][j][3] + b1;
            if (act == 1 || act == 3) {
                if (act == 1) {
                    v00 = 0.5f * v00 * (1.f + erff(v00 * 0.70710678118654752f));
                    v01 = 0.5f * v01 * (1.f + erff(v01 * 0.70710678118654752f));
                    v10 = 0.5f * v10 * (1.f + erff(v10 * 0.70710678118654752f));
                    v11 = 0.5f * v11 * (1.f + erff(v11 * 0.70710678118654752f));
                }
                __nv_bfloat16* Cb = (__nv_bfloat16*)C;
                *(__nv_bfloat162*)(Cb + (size_t)row0 * ldc + col) = __floats2bfloat162_rn(v00, v01);
                *(__nv_bfloat162*)(Cb + (size_t)row1 * ldc + col) = __floats2bfloat162_rn(v10, v11);
            } else {
                if (act == 2) {
                    const float* r0 = resid + (size_t)row0 * ldc + col;
                    const float* r1 = resid + (size_t)row1 * ldc + col;
                    v00 += r0[0]; v01 += r0[1];
                    v10 += r1[0]; v11 += r1[1];
                }
                float* Cf = (float*)C;
                *(float2*)(Cf + (size_t)row0 * ldc + col) = make_float2(v00, v01);
                *(float2*)(Cf + (size_t)row1 * ldc + col) = make_float2(v10, v11);
            }
        }
    }
}

// ---------------------------------------------------------------------------
// Attention: one block per (head, b, n).  (unchanged from best-known R11)
// ---------------------------------------------------------------------------
#define LDQ (HD + 4)
#define LDP 52

__global__ __launch_bounds__(256)
void attn_kernel(const __nv_bfloat16* __restrict__ qkv, __nv_bfloat16* __restrict__ o)
{
    __shared__ float qs[TT][LDQ];
    __shared__ float ks[TT][LDQ];
    __shared__ float vs[TT][LDQ];
    __shared__ float ps[TT][LDP];

    const int bid = blockIdx.x;
    const int n   = bid % NV;
    const int b   = (bid / NV) % MB;
    const int h   = bid / (NV * MB);
    const int tid = threadIdx.x;

    const size_t brow  = (size_t)(b * TT) * NV + n;
    const size_t qbase = brow * 1536 + h * HD;
    const size_t tq    = (size_t)NV * 1536;

    for (int idx = tid; idx < TT * (HD / 2); idx += 256) {
        int t = idx >> 5, j2 = idx & 31;
        size_t gofs = qbase + (size_t)t * tq + j2 * 2;
        float2 qv = __bfloat1622float2(*(const __nv_bfloat162*)(qkv + gofs));
        float2 kv = __bfloat1622float2(*(const __nv_bfloat162*)(qkv + gofs + 512));
        float2 vv = __bfloat1622float2(*(const __nv_bfloat162*)(qkv + gofs + 1024));
        qs[t][j2 * 2] = qv.x; qs[t][j2 * 2 + 1] = qv.y;
        ks[t][j2 * 2] = kv.x; ks[t][j2 * 2 + 1] = kv.y;
        vs[t][j2 * 2] = vv.x; vs[t][j2 * 2 + 1] = vv.y;
    }
    __syncthreads();

    // ---- scores: 78 tri-indexed 4x4 tiles, 2 lanes/tile (k-halves) ----
    {
        const int w    = tid >> 5;
        const int lane = tid & 31;
        if (w < 5) {
            const int t  = w * 16 + (lane & 15);
            const int kh = lane >> 4;
            float acc[4][4] = {};
            int i0 = 0, s0 = 0;
            const bool active = (t < 78);
            if (active) {
                int a = (int)((sqrtf(8.f * (float)t + 1.f) - 1.f) * 0.5f);
                while ((a + 1) * (a + 2) / 2 <= t) a++;
                while (a * (a + 1) / 2 > t)       a--;
                int c = t - a * (a + 1) / 2;
                i0 = a * 4; s0 = c * 4;
                #pragma unroll
                for (int c4 = 0; c4 < 8; c4++) {
                    const int cb = (kh * 8 + c4) * 4;
                    float4 qv[4], kv[4];
                    #pragma unroll
                    for (int d = 0; d < 4; d++) {
                        qv[d] = *(const float4*)&qs[i0 + d][cb];
                        kv[d] = *(const float4*)&ks[s0 + d][cb];
                    }
                    #pragma unroll
                    for (int di = 0; di < 4; di++)
                        #pragma unroll
                        for (int ds = 0; ds < 4; ds++)
                            acc[di][ds] += qv[di].x * kv[ds].x + qv[di].y * kv[ds].y
                                         + qv[di].z * kv[ds].z + qv[di].w * kv[ds].w;
                }
            }
            #pragma unroll
            for (int di = 0; di < 4; di++)
                #pragma unroll
                for (int ds = 0; ds < 4; ds++)
                    acc[di][ds] += __shfl_xor_sync(0xFFFFFFFFu, acc[di][ds], 16);
            if (active && kh == 0) {
                #pragma unroll
                for (int di = 0; di < 4; di++)
                    #pragma unroll
                    for (int ds = 0; ds < 4; ds++) {
                        int i = i0 + di, s = s0 + ds;
                        if (s <= i) ps[i][s] = acc[di][ds] * 0.125f;
                    }
            }
        }
    }
    __syncthreads();

    // ---- softmax: warp-per-row (8 warps x 6 rows), shfl reductions ----
    {
        const int w = tid >> 5, lane = tid & 31;
        #pragma unroll
        for (int r = 0; r < 6; r++) {
            const int i = w * 6 + r;
            float v0 = (lane <= i) ? ps[i][lane] : -1e30f;
            float v1 = (lane + 32 <= i) ? ps[i][lane + 32] : -1e30f;
            float mx = fmaxf(v0, v1);
            #pragma unroll
            for (int off = 16; off; off >>= 1)
                mx = fmaxf(mx, __shfl_xor_sync(0xFFFFFFFFu, mx, off));
            float e0 = (lane <= i)      ? __expf(v0 - mx) : 0.f;
            float e1 = (lane + 32 <= i) ? __expf(v1 - mx) : 0.f;
            float sum = e0 + e1;
            #pragma unroll
            for (int off = 16; off; off >>= 1)
                sum += __shfl_xor_sync(0xFFFFFFFFu, sum, off);
            float inv = 1.f / sum;
            ps[i][lane] = e0 * inv;
            if (lane + 32 < TT) ps[i][lane + 32] = e1 * inv;
        }
    }
    __syncthreads();

    // ---- O = P @ V : 256 threads, 3x4 tiles, causal truncation ----
    {
        const int i0 = (tid >> 4) * 3;
        const int j0 = (tid & 15) * 4;
        float acc[3][4] = {};
        const int send = i0 + 3;
        for (int s = 0; s < send; s++) {
            float4 vv = *(const float4*)&vs[s][j0];
            #pragma unroll
            for (int di = 0; di < 3; di++) {
                float p = ps[i0 + di][s];
                acc[di][0] += p * vv.x;
                acc[di][1] += p * vv.y;
                acc[di][2] += p * vv.z;
                acc[di][3] += p * vv.w;
            }
        }
        #pragma unroll
        for (int di = 0; di < 3; di++) {
            int i = i0 + di;
            __nv_bfloat16* op = o + (brow + (size_t)i * NV) * FF + h * HD + j0;
            *(__nv_bfloat162*)op       = __floats2bfloat162_rn(acc[di][0], acc[di][1]);
            *(__nv_bfloat162*)(op + 2) = __floats2bfloat162_rn(acc[di][2], acc[di][3]);
        }
    }
}

// ---------------------------------------------------------------------------
// LayerNorm over last dim (512). One block (128 threads) per row.
// ---------------------------------------------------------------------------
__global__ __launch_bounds__(128)
void ln_kernel(const float* __restrict__ h, const float* __restrict__ gamma,
               const float* __restrict__ beta, float* __restrict__ out)
{
    __shared__ float red[8];
    const int row = blockIdx.x;
    const int tid = threadIdx.x;

    float4 val = ((const float4*)(h + (size_t)row * FF))[tid];
    float s  = val.x + val.y + val.z + val.w;
    float ss = val.x * val.x + val.y * val.y + val.z * val.z + val.w * val.w;
    #pragma unroll
    for (int off = 16; off; off >>= 1) {
        s  += __shfl_xor_sync(0xFFFFFFFFu, s,  off);
        ss += __shfl_xor_sync(0xFFFFFFFFu, ss, off);
    }
    if ((tid & 31) == 0) { red[tid >> 5] = s; red[4 + (tid >> 5)] = ss; }
    __syncthreads();
    s  = red[0] + red[1] + red[2] + red[3];
    ss = red[4] + red[5] + red[6] + red[7];

    float mean = s * (1.f / 512.f);
    float var  = ss * (1.f / 512.f) - mean * mean;
    float rstd = rsqrtf(var + 1e-5f);

    float4 gm = ((const float4*)gamma)[tid];
    float4 bt = ((const float4*)beta)[tid];
    float4 r;
    r.x = gm.x * (val.x - mean) * rstd + bt.x;
    r.y = gm.y * (val.y - mean) * rstd + bt.y;
    r.z = gm.z * (val.z - mean) * rstd + bt.z;
    r.w = gm.w * (val.w - mean) * rstd + bt.w;
    ((float4*)(out + (size_t)row * FF))[tid] = r;
}

// ---------------------------------------------------------------------------
// Prep kernels
// ---------------------------------------------------------------------------
// x -> bf16, and the LAST block also builds the fused qkv bias vector.
__global__ void cvt_x_concat(const float* __restrict__ x, __nv_bfloat16* __restrict__ xb,
                             int n4,
                             const float* __restrict__ bq, const float* __restrict__ bk,
                             const float* __restrict__ bv, float* __restrict__ bqkv)
{
    int i = blockIdx.x * blockDim.x + threadIdx.x;
    if (i < n4) {
        float4 v = ((const float4*)x)[i];
        __nv_bfloat162* o = (__nv_bfloat162*)xb + (size_t)i * 2;
        o[0] = __floats2bfloat162_rn(v.x, v.y);
        o[1] = __floats2bfloat162_rn(v.z, v.w);
    }
    if (blockIdx.x == gridDim.x - 1) {
        for (int j = threadIdx.x; j < 1536; j += blockDim.x) {
            float v;
            if (j < 512)       v = bq[j];
            else if (j < 1024) v = bk[j - 512];
            else               v = bv[j - 1024];
            bqkv[j] = v;
        }
    }
}

// Transpose+convert a contiguous set of weight matrices (z selects which).
__global__ void transp_set(const float* __restrict__ Wa, const float* __restrict__ Wb,
                           const float* __restrict__ Wc,
                           __nv_bfloat16* __restrict__ Ta,
                           __nv_bfloat16* __restrict__ Tb,
                           __nv_bfloat16* __restrict__ Tc)
{
    __shared__ float t[32][33];
    const float* W = (blockIdx.z == 0) ? Wa : (blockIdx.z == 1) ? Wb : Wc;
    __nv_bfloat16* Wt = (blockIdx.z == 0) ? Ta : (blockIdx.z == 1) ? Tb : Tc;
    if (W == nullptr) return;
    int bx = blockIdx.x * 32, by = blockIdx.y * 32;
    int tx = threadIdx.x, ty = threadIdx.y;
    #pragma unroll
    for (int r = 0; r < 32; r += 8)
        t[ty + r][tx] = W[(size_t)(by + ty + r) * 512 + bx + tx];
    __syncthreads();
    #pragma unroll
    for (int r = 0; r < 32; r += 8)
        Wt[(size_t)(bx + ty + r) * 512 + by + tx] = __float2bfloat16(t[tx][ty + r]);
}

// ---------------------------------------------------------------------------
// Launch order note: stream = [cvt+concat, transp_qkv, QKV, attn, transp_w12,
// FFN1, FFN2, LN].  One fewer launch before attn than R11 -> the fixed ncu
// window (which captured QKV at its old index) should now land on attn_kernel.
// ---------------------------------------------------------------------------
extern "C" void kernel_launch(void* const* d_in, const int* in_sizes, int n_in,
                              void* d_out, int out_size)
{
    const float* x     = (const float*)d_in[0];
    const float* Wq    = (const float*)d_in[1];
    const float* bq    = (const float*)d_in[2];
    const float* Wk    = (const float*)d_in[3];
    const float* bk    = (const float*)d_in[4];
    const float* Wv    = (const float*)d_in[5];
    const float* bv    = (const float*)d_in[6];
    const float* W1    = (const float*)d_in[7];
    const float* b1    = (const float*)d_in[8];
    const float* W2    = (const float*)d_in[9];
    const float* b2    = (const float*)d_in[10];
    const float* gamma = (const float*)d_in[11];
    const float* beta  = (const float*)d_in[12];
    float* out = (float*)d_out;

    float* s;
    cudaGetSymbolAddress((void**)&s, g_scratch);
    __nv_bfloat16*  qkvb  = (__nv_bfloat16*)s;                     // [M,1536] bf16
    float*          h2    = s + 3 * SZ;                            // [M,512]  fp32
    __nv_bfloat16*  xb    = (__nv_bfloat16*)(s + 4 * SZ);          // [M,512]  bf16
    __nv_bfloat16*  ob    = (__nv_bfloat16*)(s + 4 * SZ + SZ / 2); // [M,512]  bf16
    __nv_bfloat16*  h1b   = (__nv_bfloat16*)(s + 5 * SZ);          // [M,512]  bf16
    __nv_bfloat16*  wqkvT = (__nv_bfloat16*)(s + 5 * SZ + SZ / 2); // [1536,512] bf16
    __nv_bfloat16*  w1T   = wqkvT + (size_t)1536 * 512;
    __nv_bfloat16*  w2T   = w1T   + (size_t)512 * 512;
    float*          bqkv  = (float*)(w2T + (size_t)512 * 512);     // [1536]

    cudaFuncSetAttribute(gemm_bf16, cudaFuncAttributeMaxDynamicSharedMemorySize, GEMM_SMEM);

    // prep (2 launches before QKV)
    cvt_x_concat<<<(int)((SZ / 4 + 255) / 256), 256>>>(
        x, xb, (int)(SZ / 4), bq, bk, bv, bqkv);
    transp_set<<<dim3(16, 16, 3), dim3(32, 8)>>>(
        Wq, Wk, Wv,
        wqkvT, wqkvT + (size_t)512 * 512, wqkvT + (size_t)1024 * 512);

    // fused QKV GEMM -> bf16 qkv
    gemm_bf16<<<dim3(1536 / BN, MROWS / BM), 128, GEMM_SMEM>>>(
        xb, wqkvT, bqkv, nullptr, qkvb, 1536, 3);

    attn_kernel<<<NHEAD * MB * NV, 256>>>(qkvb, ob);

    // W1/W2 transpose deferred here (only needed by FFN1/FFN2)
    transp_set<<<dim3(16, 16, 2), dim3(32, 8)>>>(
        W1, W2, nullptr, w1T, w2T, nullptr);

    // FFN1 (+GELU -> bf16)
    gemm_bf16<<<dim3(FF / BN, MROWS / BM), 128, GEMM_SMEM>>>(
        ob, w1T, b1, nullptr, h1b, FF, 1);
    // FFN2 (+bias +residual -> fp32)
    gemm_bf16<<<dim3(FF / BN, MROWS / BM), 128, GEMM_SMEM>>>(
        h1b, w2T, b2, x, h2, FF, 2);

    ln_kernel<<<MROWS, 128>>>(h2, gamma, beta, out);
}

// round 13
// speedup vs baseline: 1.0393x; 1.0393x over previous
#include <cuda_runtime.h>
#include <cuda_bf16.h>
#include <math.h>
#include <stdint.h>

// ---------------------------------------------------------------------------
// Problem: x [16,48,207,512], 8 heads, d=64.  M = 158976 rows, K=N=512.
// ---------------------------------------------------------------------------
#define MB   16
#define TT   48
#define NV   207
#define FF   512
#define NHEAD 8
#define HD   64
#define MROWS (MB*TT*NV)          // 158976
#define SZ   ((size_t)MROWS * FF)

__device__ float g_scratch[6 * SZ];

// ---------------------------------------------------------------------------
// helpers
// ---------------------------------------------------------------------------
__device__ __forceinline__ void cp_async16(void* smem, const void* gmem) {
    unsigned s = (unsigned)__cvta_generic_to_shared(smem);
    asm volatile("cp.async.cg.shared.global [%0], [%1], 16;\n" :: "r"(s), "l"(gmem));
}
__device__ __forceinline__ void cp_commit() { asm volatile("cp.async.commit_group;\n" ::: "memory"); }
__device__ __forceinline__ void cp_wait0()  { asm volatile("cp.async.wait_group 0;\n" ::: "memory"); }

__device__ __forceinline__ void mma_bf16(float c[4], const uint32_t a[4], const uint32_t* b) {
    asm volatile(
        "mma.sync.aligned.m16n8k16.row.col.f32.bf16.bf16.f32 "
        "{%0,%1,%2,%3}, {%4,%5,%6,%7}, {%8,%9}, {%0,%1,%2,%3};\n"
        : "+f"(c[0]), "+f"(c[1]), "+f"(c[2]), "+f"(c[3])
        : "r"(a[0]), "r"(a[1]), "r"(a[2]), "r"(a[3]), "r"(b[0]), "r"(b[1]));
}
__device__ __forceinline__ void ldsm_x4(uint32_t r[4], uint32_t addr) {
    asm volatile("ldmatrix.sync.aligned.m8n8.x4.shared.b16 {%0,%1,%2,%3}, [%4];"
                 : "=r"(r[0]), "=r"(r[1]), "=r"(r[2]), "=r"(r[3]) : "r"(addr));
}

// ---------------------------------------------------------------------------
// bf16 HMMA GEMM: C = act(A[M,512] @ Bt^T + bias) (+resid)
//   CTA tile 64x128x64, 128 threads (4 warps in n), warp tile 64x32, ldmatrix,
//   2-stage cp.async pipeline, 4 CTAs/SM (measured-best config).
//   act: 0 bias->fp32 ; 1 bias+GELU->bf16 ; 2 bias+resid->fp32 ; 3 bias->bf16
// ---------------------------------------------------------------------------
#define BM 64
#define BN 128
#define BK 64
#define LDT 72
#define KDIM 512
#define KT (KDIM / BK)   // 8
#define A_BYTES (BM * LDT * 2)            // 9216
#define B_BYTES (BN * LDT * 2)            // 18432
#define GEMM_SMEM (2 * (A_BYTES + B_BYTES))   // 55296

__global__ __launch_bounds__(128, 4)
void gemm_bf16(const __nv_bfloat16* __restrict__ A,
               const __nv_bfloat16* __restrict__ Bt,
               const float* __restrict__ bias,
               const float* __restrict__ resid,
               void* __restrict__ C, int ldc, int act)
{
    extern __shared__ __align__(16) uint8_t dsm[];

    const int tid  = threadIdx.x;
    const int m0   = blockIdx.y * BM;
    const int n0   = blockIdx.x * BN;
    const int warp = tid >> 5;
    const int lane = tid & 31;
    const int wn   = warp * 32;
    const int g    = lane >> 2;
    const int t4   = lane & 3;

    uint8_t* As[2] = { dsm,                dsm + A_BYTES };
    uint8_t* Bs[2] = { dsm + 2 * A_BYTES,  dsm + 2 * A_BYTES + B_BYTES };
    const uint32_t sm_base = (uint32_t)__cvta_generic_to_shared(dsm);

    const int lr        = lane & 7;
    const int a_row_off = ((lane >> 3) & 1) * 8;
    const int a_col_off = (lane >> 4) * 8;
    const int b_row_off = (lane >> 4) * 8;
    const int b_col_off = ((lane >> 3) & 1) * 8;

    float c[4][4][4];
    #pragma unroll
    for (int i = 0; i < 4; i++)
        #pragma unroll
        for (int j = 0; j < 4; j++)
            #pragma unroll
            for (int r = 0; r < 4; r++) c[i][j][r] = 0.f;

    auto load_tiles = [&](int kt, int buf) {
        #pragma unroll
        for (int r = 0; r < 4; r++) {
            int ch  = tid + r * 128;
            int row = ch >> 3;
            int col = (ch & 7) * 8;
            cp_async16(As[buf] + row * (LDT * 2) + col * 2,
                       A + (size_t)(m0 + row) * KDIM + kt * BK + col);
        }
        #pragma unroll
        for (int r = 0; r < 8; r++) {
            int ch  = tid + r * 128;
            int row = ch >> 3;
            int col = (ch & 7) * 8;
            cp_async16(Bs[buf] + row * (LDT * 2) + col * 2,
                       Bt + (size_t)(n0 + row) * KDIM + kt * BK + col);
        }
    };

    load_tiles(0, 0);
    cp_commit();

    for (int kt = 0; kt < KT; kt++) {
        cp_wait0();
        __syncthreads();
        if (kt + 1 < KT) {
            load_tiles(kt + 1, (kt + 1) & 1);
            cp_commit();
        }
        const int buf = kt & 1;
        const uint32_t a_base = sm_base + buf * A_BYTES;
        const uint32_t b_base = sm_base + 2 * A_BYTES + buf * B_BYTES;

        #pragma unroll
        for (int kk = 0; kk < BK; kk += 16) {
            uint32_t af[4][4];
            #pragma unroll
            for (int i = 0; i < 4; i++)
                ldsm_x4(af[i], a_base +
                        ((i * 16 + lr + a_row_off) * LDT + kk + a_col_off) * 2);
            uint32_t bfr[2][4];
            #pragma unroll
            for (int jp = 0; jp < 2; jp++)
                ldsm_x4(bfr[jp], b_base +
                        ((wn + jp * 16 + lr + b_row_off) * LDT + kk + b_col_off) * 2);
            #pragma unroll
            for (int i = 0; i < 4; i++)
                #pragma unroll
                for (int j = 0; j < 4; j++)
                    mma_bf16(c[i][j], af[i], &bfr[j >> 1][(j & 1) * 2]);
        }
        // no trailing __syncthreads (2-stage rotation ordered by top barrier)
    }

    #pragma unroll
    for (int i = 0; i < 4; i++) {
        int row0 = m0 + i * 16 + g;
        int row1 = row0 + 8;
        #pragma unroll
        for (int j = 0; j < 4; j++) {
            int col = n0 + wn + j * 8 + 2 * t4;
            float b0 = bias[col], b1 = bias[col + 1];
            float v00 = c[i][j][0] + b0;
            float v01 = c[i][j][1] + b1;
            float v10 = c[i][j][2] + b0;
            float v11 = c[i][j][3] + b1;
            if (act == 1 || act == 3) {
                if (act == 1) {
                    v00 = 0.5f * v00 * (1.f + erff(v00 * 0.70710678118654752f));
                    v01 = 0.5f * v01 * (1.f + erff(v01 * 0.70710678118654752f));
                    v10 = 0.5f * v10 * (1.f + erff(v10 * 0.70710678118654752f));
                    v11 = 0.5f * v11 * (1.f + erff(v11 * 0.70710678118654752f));
                }
                __nv_bfloat16* Cb = (__nv_bfloat16*)C;
                *(__nv_bfloat162*)(Cb + (size_t)row0 * ldc + col) = __floats2bfloat162_rn(v00, v01);
                *(__nv_bfloat162*)(Cb + (size_t)row1 * ldc + col) = __floats2bfloat162_rn(v10, v11);
            } else {
                if (act == 2) {
                    const float* r0 = resid + (size_t)row0 * ldc + col;
                    const float* r1 = resid + (size_t)row1 * ldc + col;
                    v00 += r0[0]; v01 += r0[1];
                    v10 += r1[0]; v11 += r1[1];
                }
                float* Cf = (float*)C;
                *(float2*)(Cf + (size_t)row0 * ldc + col) = make_float2(v00, v01);
                *(float2*)(Cf + (size_t)row1 * ldc + col) = make_float2(v10, v11);
            }
        }
    }
}

// ---------------------------------------------------------------------------
// Attention: one block per (head, b, n).
//   __launch_bounds__(256,4): cap 64 regs -> 4 blocks/SM (was 3, reg-limited).
//   16B gmem loads; score phase restructured for lower live-register count.
// ---------------------------------------------------------------------------
#define LDQ (HD + 4)
#define LDP 52

__global__ __launch_bounds__(256, 4)
void attn_kernel(const __nv_bfloat16* __restrict__ qkv, __nv_bfloat16* __restrict__ o)
{
    __shared__ float qs[TT][LDQ];
    __shared__ float ks[TT][LDQ];
    __shared__ float vs[TT][LDQ];
    __shared__ float ps[TT][LDP];

    const int bid = blockIdx.x;
    const int n   = bid % NV;
    const int b   = (bid / NV) % MB;
    const int h   = bid / (NV * MB);
    const int tid = threadIdx.x;

    const size_t brow  = (size_t)(b * TT) * NV + n;
    const size_t qbase = brow * 1536 + h * HD;
    const size_t tq    = (size_t)NV * 1536;

    // ---- load: 16B (8 x bf16) chunks; 3 tensors x 384 chunks ----
    for (int idx = tid; idx < 3 * TT * (HD / 8); idx += 256) {
        const int tens = idx / (TT * (HD / 8));      // 0=q, 1=k, 2=v
        const int c    = idx - tens * (TT * (HD / 8));
        const int t    = c >> 3;
        const int j8   = (c & 7) * 8;
        const __nv_bfloat16* src = qkv + qbase + (size_t)t * tq + tens * 512 + j8;
        uint4 raw = *(const uint4*)src;
        const __nv_bfloat162* p2 = (const __nv_bfloat162*)&raw;
        float* dst = (tens == 0) ? &qs[t][j8] : (tens == 1) ? &ks[t][j8] : &vs[t][j8];
        float4 lo, hi;
        float2 a0 = __bfloat1622float2(p2[0]);
        float2 a1 = __bfloat1622float2(p2[1]);
        float2 a2 = __bfloat1622float2(p2[2]);
        float2 a3 = __bfloat1622float2(p2[3]);
        lo.x = a0.x; lo.y = a0.y; lo.z = a1.x; lo.w = a1.y;
        hi.x = a2.x; hi.y = a2.y; hi.z = a3.x; hi.w = a3.y;
        *(float4*)dst       = lo;
        *(float4*)(dst + 4) = hi;
    }
    __syncthreads();

    // ---- scores: 78 tri-indexed 4x4 tiles, 2 lanes/tile (k-halves) ----
    {
        const int w    = tid >> 5;
        const int lane = tid & 31;
        if (w < 5) {
            const int t  = w * 16 + (lane & 15);
            const int kh = lane >> 4;
            float acc[4][4] = {};
            int i0 = 0, s0 = 0;
            const bool active = (t < 78);
            if (active) {
                int a = (int)((sqrtf(8.f * (float)t + 1.f) - 1.f) * 0.5f);
                while ((a + 1) * (a + 2) / 2 <= t) a++;
                while (a * (a + 1) / 2 > t)       a--;
                int c = t - a * (a + 1) / 2;
                i0 = a * 4; s0 = c * 4;
                #pragma unroll
                for (int c4 = 0; c4 < 8; c4++) {
                    const int cb = (kh * 8 + c4) * 4;
                    float4 kv[4];
                    #pragma unroll
                    for (int d = 0; d < 4; d++)
                        kv[d] = *(const float4*)&ks[s0 + d][cb];
                    #pragma unroll
                    for (int di = 0; di < 4; di++) {
                        float4 qv = *(const float4*)&qs[i0 + di][cb];
                        #pragma unroll
                        for (int ds = 0; ds < 4; ds++)
                            acc[di][ds] += qv.x * kv[ds].x + qv.y * kv[ds].y
                                         + qv.z * kv[ds].z + qv.w * kv[ds].w;
                    }
                }
            }
            #pragma unroll
            for (int di = 0; di < 4; di++)
                #pragma unroll
                for (int ds = 0; ds < 4; ds++)
                    acc[di][ds] += __shfl_xor_sync(0xFFFFFFFFu, acc[di][ds], 16);
            if (active && kh == 0) {
                #pragma unroll
                for (int di = 0; di < 4; di++)
                    #pragma unroll
                    for (int ds = 0; ds < 4; ds++) {
                        int i = i0 + di, s = s0 + ds;
                        if (s <= i) ps[i][s] = acc[di][ds] * 0.125f;
                    }
            }
        }
    }
    __syncthreads();

    // ---- softmax: warp-per-row (8 warps x 6 rows), shfl reductions ----
    {
        const int w = tid >> 5, lane = tid & 31;
        #pragma unroll
        for (int r = 0; r < 6; r++) {
            const int i = w * 6 + r;
            float v0 = (lane <= i) ? ps[i][lane] : -1e30f;
            float v1 = (lane + 32 <= i) ? ps[i][lane + 32] : -1e30f;
            float mx = fmaxf(v0, v1);
            #pragma unroll
            for (int off = 16; off; off >>= 1)
                mx = fmaxf(mx, __shfl_xor_sync(0xFFFFFFFFu, mx, off));
            float e0 = (lane <= i)      ? __expf(v0 - mx) : 0.f;
            float e1 = (lane + 32 <= i) ? __expf(v1 - mx) : 0.f;
            float sum = e0 + e1;
            #pragma unroll
            for (int off = 16; off; off >>= 1)
                sum += __shfl_xor_sync(0xFFFFFFFFu, sum, off);
            float inv = 1.f / sum;
            ps[i][lane] = e0 * inv;
            if (lane + 32 < TT) ps[i][lane + 32] = e1 * inv;
        }
    }
    __syncthreads();

    // ---- O = P @ V : 256 threads, 3x4 tiles, causal truncation ----
    {
        const int i0 = (tid >> 4) * 3;
        const int j0 = (tid & 15) * 4;
        float acc[3][4] = {};
        const int send = i0 + 3;
        for (int s = 0; s < send; s++) {
            float4 vv = *(const float4*)&vs[s][j0];
            #pragma unroll
            for (int di = 0; di < 3; di++) {
                float p = ps[i0 + di][s];
                acc[di][0] += p * vv.x;
                acc[di][1] += p * vv.y;
                acc[di][2] += p * vv.z;
                acc[di][3] += p * vv.w;
            }
        }
        #pragma unroll
        for (int di = 0; di < 3; di++) {
            int i = i0 + di;
            __nv_bfloat16* op = o + (brow + (size_t)i * NV) * FF + h * HD + j0;
            *(__nv_bfloat162*)op       = __floats2bfloat162_rn(acc[di][0], acc[di][1]);
            *(__nv_bfloat162*)(op + 2) = __floats2bfloat162_rn(acc[di][2], acc[di][3]);
        }
    }
}

// ---------------------------------------------------------------------------
// LayerNorm over last dim (512). One block (128 threads) per row.
// ---------------------------------------------------------------------------
__global__ __launch_bounds__(128)
void ln_kernel(const float* __restrict__ h, const float* __restrict__ gamma,
               const float* __restrict__ beta, float* __restrict__ out)
{
    __shared__ float red[8];
    const int row = blockIdx.x;
    const int tid = threadIdx.x;

    float4 val = ((const float4*)(h + (size_t)row * FF))[tid];
    float s  = val.x + val.y + val.z + val.w;
    float ss = val.x * val.x + val.y * val.y + val.z * val.z + val.w * val.w;
    #pragma unroll
    for (int off = 16; off; off >>= 1) {
        s  += __shfl_xor_sync(0xFFFFFFFFu, s,  off);
        ss += __shfl_xor_sync(0xFFFFFFFFu, ss, off);
    }
    if ((tid & 31) == 0) { red[tid >> 5] = s; red[4 + (tid >> 5)] = ss; }
    __syncthreads();
    s  = red[0] + red[1] + red[2] + red[3];
    ss = red[4] + red[5] + red[6] + red[7];

    float mean = s * (1.f / 512.f);
    float var  = ss * (1.f / 512.f) - mean * mean;
    float rstd = rsqrtf(var + 1e-5f);

    float4 gm = ((const float4*)gamma)[tid];
    float4 bt = ((const float4*)beta)[tid];
    float4 r;
    r.x = gm.x * (val.x - mean) * rstd + bt.x;
    r.y = gm.y * (val.y - mean) * rstd + bt.y;
    r.z = gm.z * (val.z - mean) * rstd + bt.z;
    r.w = gm.w * (val.w - mean) * rstd + bt.w;
    ((float4*)(out + (size_t)row * FF))[tid] = r;
}

// ---------------------------------------------------------------------------
// Prep kernels
// ---------------------------------------------------------------------------
__global__ void cvt_x_concat(const float* __restrict__ x, __nv_bfloat16* __restrict__ xb,
                             int n4,
                             const float* __restrict__ bq, const float* __restrict__ bk,
                             const float* __restrict__ bv, float* __restrict__ bqkv)
{
    int i = blockIdx.x * blockDim.x + threadIdx.x;
    if (i < n4) {
        float4 v = ((const float4*)x)[i];
        __nv_bfloat162* o = (__nv_bfloat162*)xb + (size_t)i * 2;
        o[0] = __floats2bfloat162_rn(v.x, v.y);
        o[1] = __floats2bfloat162_rn(v.z, v.w);
    }
    if (blockIdx.x == gridDim.x - 1) {
        for (int j = threadIdx.x; j < 1536; j += blockDim.x) {
            float v;
            if (j < 512)       v = bq[j];
            else if (j < 1024) v = bk[j - 512];
            else               v = bv[j - 1024];
            bqkv[j] = v;
        }
    }
}

__global__ void transp_set(const float* __restrict__ Wa, const float* __restrict__ Wb,
                           const float* __restrict__ Wc,
                           __nv_bfloat16* __restrict__ Ta,
                           __nv_bfloat16* __restrict__ Tb,
                           __nv_bfloat16* __restrict__ Tc)
{
    __shared__ float t[32][33];
    const float* W = (blockIdx.z == 0) ? Wa : (blockIdx.z == 1) ? Wb : Wc;
    __nv_bfloat16* Wt = (blockIdx.z == 0) ? Ta : (blockIdx.z == 1) ? Tb : Tc;
    if (W == nullptr) return;
    int bx = blockIdx.x * 32, by = blockIdx.y * 32;
    int tx = threadIdx.x, ty = threadIdx.y;
    #pragma unroll
    for (int r = 0; r < 32; r += 8)
        t[ty + r][tx] = W[(size_t)(by + ty + r) * 512 + bx + tx];
    __syncthreads();
    #pragma unroll
    for (int r = 0; r < 32; r += 8)
        Wt[(size_t)(bx + ty + r) * 512 + by + tx] = __float2bfloat16(t[tx][ty + r]);
}

// ---------------------------------------------------------------------------
// Launch
// ---------------------------------------------------------------------------
extern "C" void kernel_launch(void* const* d_in, const int* in_sizes, int n_in,
                              void* d_out, int out_size)
{
    const float* x     = (const float*)d_in[0];
    const float* Wq    = (const float*)d_in[1];
    const float* bq    = (const float*)d_in[2];
    const float* Wk    = (const float*)d_in[3];
    const float* bk    = (const float*)d_in[4];
    const float* Wv    = (const float*)d_in[5];
    const float* bv    = (const float*)d_in[6];
    const float* W1    = (const float*)d_in[7];
    const float* b1    = (const float*)d_in[8];
    const float* W2    = (const float*)d_in[9];
    const float* b2    = (const float*)d_in[10];
    const float* gamma = (const float*)d_in[11];
    const float* beta  = (const float*)d_in[12];
    float* out = (float*)d_out;

    float* s;
    cudaGetSymbolAddress((void**)&s, g_scratch);
    __nv_bfloat16*  qkvb  = (__nv_bfloat16*)s;                     // [M,1536] bf16
    float*          h2    = s + 3 * SZ;                            // [M,512]  fp32
    __nv_bfloat16*  xb    = (__nv_bfloat16*)(s + 4 * SZ);          // [M,512]  bf16
    __nv_bfloat16*  ob    = (__nv_bfloat16*)(s + 4 * SZ + SZ / 2); // [M,512]  bf16
    __nv_bfloat16*  h1b   = (__nv_bfloat16*)(s + 5 * SZ);          // [M,512]  bf16
    __nv_bfloat16*  wqkvT = (__nv_bfloat16*)(s + 5 * SZ + SZ / 2); // [1536,512] bf16
    __nv_bfloat16*  w1T   = wqkvT + (size_t)1536 * 512;
    __nv_bfloat16*  w2T   = w1T   + (size_t)512 * 512;
    float*          bqkv  = (float*)(w2T + (size_t)512 * 512);     // [1536]

    cudaFuncSetAttribute(gemm_bf16, cudaFuncAttributeMaxDynamicSharedMemorySize, GEMM_SMEM);

    // prep (2 launches before QKV)
    cvt_x_concat<<<(int)((SZ / 4 + 255) / 256), 256>>>(
        x, xb, (int)(SZ / 4), bq, bk, bv, bqkv);
    transp_set<<<dim3(16, 16, 3), dim3(32, 8)>>>(
        Wq, Wk, Wv,
        wqkvT, wqkvT + (size_t)512 * 512, wqkvT + (size_t)1024 * 512);

    // fused QKV GEMM -> bf16 qkv
    gemm_bf16<<<dim3(1536 / BN, MROWS / BM), 128, GEMM_SMEM>>>(
        xb, wqkvT, bqkv, nullptr, qkvb, 1536, 3);

    attn_kernel<<<NHEAD * MB * NV, 256>>>(qkvb, ob);

    // W1/W2 transpose deferred (only needed by FFN1/FFN2)
    transp_set<<<dim3(16, 16, 2), dim3(32, 8)>>>(
        W1, W2, nullptr, w1T, w2T, nullptr);

    // FFN1 (+GELU -> bf16)
    gemm_bf16<<<dim3(FF / BN, MROWS / BM), 128, GEMM_SMEM>>>(
        ob, w1T, b1, nullptr, h1b, FF, 1);
    // FFN2 (+bias +residual -> fp32)
    gemm_bf16<<<dim3(FF / BN, MROWS / BM), 128, GEMM_SMEM>>>(
        h1b, w2T, b2, x, h2, FF, 2);

    ln_kernel<<<MROWS, 128>>>(h2, gamma, beta, out);
}

// round 14
// speedup vs baseline: 1.0878x; 1.0466x over previous
#include <cuda_runtime.h>
#include <cuda_bf16.h>
#include <math.h>
#include <stdint.h>

// ---------------------------------------------------------------------------
// Problem: x [16,48,207,512], 8 heads, d=64.  M = 158976 rows, K=N=512.
// ---------------------------------------------------------------------------
#define MB   16
#define TT   48
#define NV   207
#define FF   512
#define NHEAD 8
#define HD   64
#define MROWS (MB*TT*NV)          // 158976
#define SZ   ((size_t)MROWS * FF)

__device__ float g_scratch[6 * SZ];

// ---------------------------------------------------------------------------
// helpers
// ---------------------------------------------------------------------------
__device__ __forceinline__ void cp_async16(void* smem, const void* gmem) {
    unsigned s = (unsigned)__cvta_generic_to_shared(smem);
    asm volatile("cp.async.cg.shared.global [%0], [%1], 16;\n" :: "r"(s), "l"(gmem));
}
__device__ __forceinline__ void cp_commit() { asm volatile("cp.async.commit_group;\n" ::: "memory"); }
__device__ __forceinline__ void cp_wait0()  { asm volatile("cp.async.wait_group 0;\n" ::: "memory"); }

__device__ __forceinline__ void mma_bf16(float c[4], const uint32_t a[4], const uint32_t* b) {
    asm volatile(
        "mma.sync.aligned.m16n8k16.row.col.f32.bf16.bf16.f32 "
        "{%0,%1,%2,%3}, {%4,%5,%6,%7}, {%8,%9}, {%0,%1,%2,%3};\n"
        : "+f"(c[0]), "+f"(c[1]), "+f"(c[2]), "+f"(c[3])
        : "r"(a[0]), "r"(a[1]), "r"(a[2]), "r"(a[3]), "r"(b[0]), "r"(b[1]));
}
__device__ __forceinline__ void ldsm_x4(uint32_t r[4], uint32_t addr) {
    asm volatile("ldmatrix.sync.aligned.m8n8.x4.shared.b16 {%0,%1,%2,%3}, [%4];"
                 : "=r"(r[0]), "=r"(r[1]), "=r"(r[2]), "=r"(r[3]) : "r"(addr));
}

// ---------------------------------------------------------------------------
// bf16 HMMA GEMM: C = act(A[M,512] @ Bt^T + bias) (+resid)
//   CTA tile 64x128x64, 128 threads (4 warps in n), warp tile 64x32, ldmatrix,
//   2-stage cp.async pipeline, 4 CTAs/SM (measured-best config).
//   act: 0 bias->fp32 ; 1 bias+GELU->bf16 ; 2 bias+resid->fp32 ; 3 bias->bf16
// ---------------------------------------------------------------------------
#define BM 64
#define BN 128
#define BK 64
#define LDT 72
#define KDIM 512
#define KT (KDIM / BK)   // 8
#define A_BYTES (BM * LDT * 2)            // 9216
#define B_BYTES (BN * LDT * 2)            // 18432
#define GEMM_SMEM (2 * (A_BYTES + B_BYTES))   // 55296

__global__ __launch_bounds__(128, 4)
void gemm_bf16(const __nv_bfloat16* __restrict__ A,
               const __nv_bfloat16* __restrict__ Bt,
               const float* __restrict__ bias,
               const float* __restrict__ resid,
               void* __restrict__ C, int ldc, int act)
{
    extern __shared__ __align__(16) uint8_t dsm[];

    const int tid  = threadIdx.x;
    const int m0   = blockIdx.y * BM;
    const int n0   = blockIdx.x * BN;
    const int warp = tid >> 5;
    const int lane = tid & 31;
    const int wn   = warp * 32;
    const int g    = lane >> 2;
    const int t4   = lane & 3;

    uint8_t* As[2] = { dsm,                dsm + A_BYTES };
    uint8_t* Bs[2] = { dsm + 2 * A_BYTES,  dsm + 2 * A_BYTES + B_BYTES };
    const uint32_t sm_base = (uint32_t)__cvta_generic_to_shared(dsm);

    const int lr        = lane & 7;
    const int a_row_off = ((lane >> 3) & 1) * 8;
    const int a_col_off = (lane >> 4) * 8;
    const int b_row_off = (lane >> 4) * 8;
    const int b_col_off = ((lane >> 3) & 1) * 8;

    float c[4][4][4];
    #pragma unroll
    for (int i = 0; i < 4; i++)
        #pragma unroll
        for (int j = 0; j < 4; j++)
            #pragma unroll
            for (int r = 0; r < 4; r++) c[i][j][r] = 0.f;

    auto load_tiles = [&](int kt, int buf) {
        #pragma unroll
        for (int r = 0; r < 4; r++) {
            int ch  = tid + r * 128;
            int row = ch >> 3;
            int col = (ch & 7) * 8;
            cp_async16(As[buf] + row * (LDT * 2) + col * 2,
                       A + (size_t)(m0 + row) * KDIM + kt * BK + col);
        }
        #pragma unroll
        for (int r = 0; r < 8; r++) {
            int ch  = tid + r * 128;
            int row = ch >> 3;
            int col = (ch & 7) * 8;
            cp_async16(Bs[buf] + row * (LDT * 2) + col * 2,
                       Bt + (size_t)(n0 + row) * KDIM + kt * BK + col);
        }
    };

    load_tiles(0, 0);
    cp_commit();

    for (int kt = 0; kt < KT; kt++) {
        cp_wait0();
        __syncthreads();
        if (kt + 1 < KT) {
            load_tiles(kt + 1, (kt + 1) & 1);
            cp_commit();
        }
        const int buf = kt & 1;
        const uint32_t a_base = sm_base + buf * A_BYTES;
        const uint32_t b_base = sm_base + 2 * A_BYTES + buf * B_BYTES;

        #pragma unroll
        for (int kk = 0; kk < BK; kk += 16) {
            uint32_t af[4][4];
            #pragma unroll
            for (int i = 0; i < 4; i++)
                ldsm_x4(af[i], a_base +
                        ((i * 16 + lr + a_row_off) * LDT + kk + a_col_off) * 2);
            uint32_t bfr[2][4];
            #pragma unroll
            for (int jp = 0; jp < 2; jp++)
                ldsm_x4(bfr[jp], b_base +
                        ((wn + jp * 16 + lr + b_row_off) * LDT + kk + b_col_off) * 2);
            #pragma unroll
            for (int i = 0; i < 4; i++)
                #pragma unroll
                for (int j = 0; j < 4; j++)
                    mma_bf16(c[i][j], af[i], &bfr[j >> 1][(j & 1) * 2]);
        }
        // no trailing __syncthreads (2-stage rotation ordered by top barrier)
    }

    #pragma unroll
    for (int i = 0; i < 4; i++) {
        int row0 = m0 + i * 16 + g;
        int row1 = row0 + 8;
        #pragma unroll
        for (int j = 0; j < 4; j++) {
            int col = n0 + wn + j * 8 + 2 * t4;
            float b0 = bias[col], b1 = bias[col + 1];
            float v00 = c[i][j][0] + b0;
            float v01 = c[i][j][1] + b1;
            float v10 = c[i][j][2] + b0;
            float v11 = c[i][j][3] + b1;
            if (act == 1 || act == 3) {
                if (act == 1) {
                    v00 = 0.5f * v00 * (1.f + erff(v00 * 0.70710678118654752f));
                    v01 = 0.5f * v01 * (1.f + erff(v01 * 0.70710678118654752f));
                    v10 = 0.5f * v10 * (1.f + erff(v10 * 0.70710678118654752f));
                    v11 = 0.5f * v11 * (1.f + erff(v11 * 0.70710678118654752f));
                }
                __nv_bfloat16* Cb = (__nv_bfloat16*)C;
                *(__nv_bfloat162*)(Cb + (size_t)row0 * ldc + col) = __floats2bfloat162_rn(v00, v01);
                *(__nv_bfloat162*)(Cb + (size_t)row1 * ldc + col) = __floats2bfloat162_rn(v10, v11);
            } else {
                if (act == 2) {
                    const float* r0 = resid + (size_t)row0 * ldc + col;
                    const float* r1 = resid + (size_t)row1 * ldc + col;
                    v00 += r0[0]; v01 += r0[1];
                    v10 += r1[0]; v11 += r1[1];
                }
                float* Cf = (float*)C;
                *(float2*)(Cf + (size_t)row0 * ldc + col) = make_float2(v00, v01);
                *(float2*)(Cf + (size_t)row1 * ldc + col) = make_float2(v10, v11);
            }
        }
    }
}

// ---------------------------------------------------------------------------
// Attention: one block per (head, b, n).
//   q/k/v held in smem as RAW bf16 (uint32 pairs) -> half the LDS bytes.
//   Convert to fp32 in registers at use (bit-identical math vs fp32 smem,
//   since gmem qkv is already bf16).
// ---------------------------------------------------------------------------
#define LDQB 36          // uints per row (32 data + 4 pad): 144B, 16B-aligned
#define LDP 52

__global__ __launch_bounds__(256, 4)
void attn_kernel(const __nv_bfloat16* __restrict__ qkv, __nv_bfloat16* __restrict__ o)
{
    __shared__ uint32_t qs[TT][LDQB];
    __shared__ uint32_t ks[TT][LDQB];
    __shared__ uint32_t vs[TT][LDQB];
    __shared__ float ps[TT][LDP];

    const int bid = blockIdx.x;
    const int n   = bid % NV;
    const int b   = (bid / NV) % MB;
    const int h   = bid / (NV * MB);
    const int tid = threadIdx.x;

    const size_t brow  = (size_t)(b * TT) * NV + n;
    const size_t qbase = brow * 1536 + h * HD;
    const size_t tq    = (size_t)NV * 1536;

    // ---- load: raw 16B chunks (8 bf16 = 4 uints); 3 x 384 = 1152 chunks ----
    for (int idx = tid; idx < 3 * TT * (HD / 8); idx += 256) {
        const int tens = idx / (TT * (HD / 8));
        const int c    = idx - tens * (TT * (HD / 8));
        const int t    = c >> 3;
        const int j4   = (c & 7) * 4;                 // uint offset in row
        const __nv_bfloat16* src = qkv + qbase + (size_t)t * tq + tens * 512 + j4 * 2;
        uint4 raw = *(const uint4*)src;
        uint32_t* dst = (tens == 0) ? &qs[t][j4] : (tens == 1) ? &ks[t][j4] : &vs[t][j4];
        *(uint4*)dst = raw;
    }
    __syncthreads();

    // ---- scores: 78 tri-indexed 4x4 tiles, 2 lanes/tile (k-halves) ----
    {
        const int w    = tid >> 5;
        const int lane = tid & 31;
        if (w < 5) {
            const int t  = w * 16 + (lane & 15);
            const int kh = lane >> 4;                 // half: chunks [kh*4, kh*4+4)
            float acc[4][4] = {};
            int i0 = 0, s0 = 0;
            const bool active = (t < 78);
            if (active) {
                int a = (int)((sqrtf(8.f * (float)t + 1.f) - 1.f) * 0.5f);
                while ((a + 1) * (a + 2) / 2 <= t) a++;
                while (a * (a + 1) / 2 > t)       a--;
                int c = t - a * (a + 1) / 2;
                i0 = a * 4; s0 = c * 4;
                #pragma unroll
                for (int c8 = 0; c8 < 4; c8++) {
                    const int cu = (kh * 4 + c8) * 4;     // uint index of 8-elem chunk
                    float2 kf[4][4];
                    #pragma unroll
                    for (int d = 0; d < 4; d++) {
                        uint4 kraw = *(const uint4*)&ks[s0 + d][cu];
                        kf[d][0] = __bfloat1622float2(*(__nv_bfloat162*)&kraw.x);
                        kf[d][1] = __bfloat1622float2(*(__nv_bfloat162*)&kraw.y);
                        kf[d][2] = __bfloat1622float2(*(__nv_bfloat162*)&kraw.z);
                        kf[d][3] = __bfloat1622float2(*(__nv_bfloat162*)&kraw.w);
                    }
                    #pragma unroll
                    for (int di = 0; di < 4; di++) {
                        uint4 qraw = *(const uint4*)&qs[i0 + di][cu];
                        float2 qf0 = __bfloat1622float2(*(__nv_bfloat162*)&qraw.x);
                        float2 qf1 = __bfloat1622float2(*(__nv_bfloat162*)&qraw.y);
                        float2 qf2 = __bfloat1622float2(*(__nv_bfloat162*)&qraw.z);
                        float2 qf3 = __bfloat1622float2(*(__nv_bfloat162*)&qraw.w);
                        #pragma unroll
                        for (int ds = 0; ds < 4; ds++)
                            acc[di][ds] += qf0.x * kf[ds][0].x + qf0.y * kf[ds][0].y
                                         + qf1.x * kf[ds][1].x + qf1.y * kf[ds][1].y
                                         + qf2.x * kf[ds][2].x + qf2.y * kf[ds][2].y
                                         + qf3.x * kf[ds][3].x + qf3.y * kf[ds][3].y;
                    }
                }
            }
            #pragma unroll
            for (int di = 0; di < 4; di++)
                #pragma unroll
                for (int ds = 0; ds < 4; ds++)
                    acc[di][ds] += __shfl_xor_sync(0xFFFFFFFFu, acc[di][ds], 16);
            if (active && kh == 0) {
                #pragma unroll
                for (int di = 0; di < 4; di++)
                    #pragma unroll
                    for (int ds = 0; ds < 4; ds++) {
                        int i = i0 + di, s = s0 + ds;
                        if (s <= i) ps[i][s] = acc[di][ds] * 0.125f;
                    }
            }
        }
    }
    __syncthreads();

    // ---- softmax: warp-per-row (8 warps x 6 rows), shfl reductions ----
    {
        const int w = tid >> 5, lane = tid & 31;
        #pragma unroll
        for (int r = 0; r < 6; r++) {
            const int i = w * 6 + r;
            float v0 = (lane <= i) ? ps[i][lane] : -1e30f;
            float v1 = (lane + 32 <= i) ? ps[i][lane + 32] : -1e30f;
            float mx = fmaxf(v0, v1);
            #pragma unroll
            for (int off = 16; off; off >>= 1)
                mx = fmaxf(mx, __shfl_xor_sync(0xFFFFFFFFu, mx, off));
            float e0 = (lane <= i)      ? __expf(v0 - mx) : 0.f;
            float e1 = (lane + 32 <= i) ? __expf(v1 - mx) : 0.f;
            float sum = e0 + e1;
            #pragma unroll
            for (int off = 16; off; off >>= 1)
                sum += __shfl_xor_sync(0xFFFFFFFFu, sum, off);
            float inv = 1.f / sum;
            ps[i][lane] = e0 * inv;
            if (lane + 32 < TT) ps[i][lane + 32] = e1 * inv;
        }
    }
    __syncthreads();

    // ---- O = P @ V : 256 threads, 3x4 tiles, causal truncation ----
    {
        const int i0  = (tid >> 4) * 3;
        const int j0u = (tid & 15) * 2;               // uint index: 4 bf16 cols
        float acc[3][4] = {};
        const int send = i0 + 3;
        for (int s = 0; s < send; s++) {
            uint2 vraw = *(const uint2*)&vs[s][j0u];
            float2 v01 = __bfloat1622float2(*(__nv_bfloat162*)&vraw.x);
            float2 v23 = __bfloat1622float2(*(__nv_bfloat162*)&vraw.y);
            #pragma unroll
            for (int di = 0; di < 3; di++) {
                float p = ps[i0 + di][s];
                acc[di][0] += p * v01.x;
                acc[di][1] += p * v01.y;
                acc[di][2] += p * v23.x;
                acc[di][3] += p * v23.y;
            }
        }
        #pragma unroll
        for (int di = 0; di < 3; di++) {
            int i = i0 + di;
            __nv_bfloat16* op = o + (brow + (size_t)i * NV) * FF + h * HD + j0u * 2;
            *(__nv_bfloat162*)op       = __floats2bfloat162_rn(acc[di][0], acc[di][1]);
            *(__nv_bfloat162*)(op + 2) = __floats2bfloat162_rn(acc[di][2], acc[di][3]);
        }
    }
}

// ---------------------------------------------------------------------------
// LayerNorm over last dim (512). One block (128 threads) per row.
// ---------------------------------------------------------------------------
__global__ __launch_bounds__(128)
void ln_kernel(const float* __restrict__ h, const float* __restrict__ gamma,
               const float* __restrict__ beta, float* __restrict__ out)
{
    __shared__ float red[8];
    const int row = blockIdx.x;
    const int tid = threadIdx.x;

    float4 val = ((const float4*)(h + (size_t)row * FF))[tid];
    float s  = val.x + val.y + val.z + val.w;
    float ss = val.x * val.x + val.y * val.y + val.z * val.z + val.w * val.w;
    #pragma unroll
    for (int off = 16; off; off >>= 1) {
        s  += __shfl_xor_sync(0xFFFFFFFFu, s,  off);
        ss += __shfl_xor_sync(0xFFFFFFFFu, ss, off);
    }
    if ((tid & 31) == 0) { red[tid >> 5] = s; red[4 + (tid >> 5)] = ss; }
    __syncthreads();
    s  = red[0] + red[1] + red[2] + red[3];
    ss = red[4] + red[5] + red[6] + red[7];

    float mean = s * (1.f / 512.f);
    float var  = ss * (1.f / 512.f) - mean * mean;
    float rstd = rsqrtf(var + 1e-5f);

    float4 gm = ((const float4*)gamma)[tid];
    float4 bt = ((const float4*)beta)[tid];
    float4 r;
    r.x = gm.x * (val.x - mean) * rstd + bt.x;
    r.y = gm.y * (val.y - mean) * rstd + bt.y;
    r.z = gm.z * (val.z - mean) * rstd + bt.z;
    r.w = gm.w * (val.w - mean) * rstd + bt.w;
    ((float4*)(out + (size_t)row * FF))[tid] = r;
}

// ---------------------------------------------------------------------------
// Prep kernels
// ---------------------------------------------------------------------------
__global__ void cvt_x_concat(const float* __restrict__ x, __nv_bfloat16* __restrict__ xb,
                             int n4,
                             const float* __restrict__ bq, const float* __restrict__ bk,
                             const float* __restrict__ bv, float* __restrict__ bqkv)
{
    int i = blockIdx.x * blockDim.x + threadIdx.x;
    if (i < n4) {
        float4 v = ((const float4*)x)[i];
        __nv_bfloat162* o = (__nv_bfloat162*)xb + (size_t)i * 2;
        o[0] = __floats2bfloat162_rn(v.x, v.y);
        o[1] = __floats2bfloat162_rn(v.z, v.w);
    }
    if (blockIdx.x == gridDim.x - 1) {
        for (int j = threadIdx.x; j < 1536; j += blockDim.x) {
            float v;
            if (j < 512)       v = bq[j];
            else if (j < 1024) v = bk[j - 512];
            else               v = bv[j - 1024];
            bqkv[j] = v;
        }
    }
}

__global__ void transp_set(const float* __restrict__ Wa, const float* __restrict__ Wb,
                           const float* __restrict__ Wc,
                           __nv_bfloat16* __restrict__ Ta,
                           __nv_bfloat16* __restrict__ Tb,
                           __nv_bfloat16* __restrict__ Tc)
{
    __shared__ float t[32][33];
    const float* W = (blockIdx.z == 0) ? Wa : (blockIdx.z == 1) ? Wb : Wc;
    __nv_bfloat16* Wt = (blockIdx.z == 0) ? Ta : (blockIdx.z == 1) ? Tb : Tc;
    if (W == nullptr) return;
    int bx = blockIdx.x * 32, by = blockIdx.y * 32;
    int tx = threadIdx.x, ty = threadIdx.y;
    #pragma unroll
    for (int r = 0; r < 32; r += 8)
        t[ty + r][tx] = W[(size_t)(by + ty + r) * 512 + bx + tx];
    __syncthreads();
    #pragma unroll
    for (int r = 0; r < 32; r += 8)
        Wt[(size_t)(bx + ty + r) * 512 + by + tx] = __float2bfloat16(t[tx][ty + r]);
}

// ---------------------------------------------------------------------------
// Launch
// ---------------------------------------------------------------------------
extern "C" void kernel_launch(void* const* d_in, const int* in_sizes, int n_in,
                              void* d_out, int out_size)
{
    const float* x     = (const float*)d_in[0];
    const float* Wq    = (const float*)d_in[1];
    const float* bq    = (const float*)d_in[2];
    const float* Wk    = (const float*)d_in[3];
    const float* bk    = (const float*)d_in[4];
    const float* Wv    = (const float*)d_in[5];
    const float* bv    = (const float*)d_in[6];
    const float* W1    = (const float*)d_in[7];
    const float* b1    = (const float*)d_in[8];
    const float* W2    = (const float*)d_in[9];
    const float* b2    = (const float*)d_in[10];
    const float* gamma = (const float*)d_in[11];
    const float* beta  = (const float*)d_in[12];
    float* out = (float*)d_out;

    float* s;
    cudaGetSymbolAddress((void**)&s, g_scratch);
    __nv_bfloat16*  qkvb  = (__nv_bfloat16*)s;                     // [M,1536] bf16
    float*          h2    = s + 3 * SZ;                            // [M,512]  fp32
    __nv_bfloat16*  xb    = (__nv_bfloat16*)(s + 4 * SZ);          // [M,512]  bf16
    __nv_bfloat16*  ob    = (__nv_bfloat16*)(s + 4 * SZ + SZ / 2); // [M,512]  bf16
    __nv_bfloat16*  h1b   = (__nv_bfloat16*)(s + 5 * SZ);          // [M,512]  bf16
    __nv_bfloat16*  wqkvT = (__nv_bfloat16*)(s + 5 * SZ + SZ / 2); // [1536,512] bf16
    __nv_bfloat16*  w1T   = wqkvT + (size_t)1536 * 512;
    __nv_bfloat16*  w2T   = w1T   + (size_t)512 * 512;
    float*          bqkv  = (float*)(w2T + (size_t)512 * 512);     // [1536]

    cudaFuncSetAttribute(gemm_bf16, cudaFuncAttributeMaxDynamicSharedMemorySize, GEMM_SMEM);

    // prep (2 launches before QKV)
    cvt_x_concat<<<(int)((SZ / 4 + 255) / 256), 256>>>(
        x, xb, (int)(SZ / 4), bq, bk, bv, bqkv);
    transp_set<<<dim3(16, 16, 3), dim3(32, 8)>>>(
        Wq, Wk, Wv,
        wqkvT, wqkvT + (size_t)512 * 512, wqkvT + (size_t)1024 * 512);

    // fused QKV GEMM -> bf16 qkv
    gemm_bf16<<<dim3(1536 / BN, MROWS / BM), 128, GEMM_SMEM>>>(
        xb, wqkvT, bqkv, nullptr, qkvb, 1536, 3);

    attn_kernel<<<NHEAD * MB * NV, 256>>>(qkvb, ob);

    // W1/W2 transpose deferred (only needed by FFN1/FFN2)
    transp_set<<<dim3(16, 16, 2), dim3(32, 8)>>>(
        W1, W2, nullptr, w1T, w2T, nullptr);

    // FFN1 (+GELU -> bf16)
    gemm_bf16<<<dim3(FF / BN, MROWS / BM), 128, GEMM_SMEM>>>(
        ob, w1T, b1, nullptr, h1b, FF, 1);
    // FFN2 (+bias +residual -> fp32)
    gemm_bf16<<<dim3(FF / BN, MROWS / BM), 128, GEMM_SMEM>>>(
        h1b, w2T, b2, x, h2, FF, 2);

    ln_kernel<<<MROWS, 128>>>(h2, gamma, beta, out);
}

// round 15
// speedup vs baseline: 1.1989x; 1.1022x over previous
#include <cuda_runtime.h>
#include <cuda_bf16.h>
#include <math.h>
#include <stdint.h>

// ---------------------------------------------------------------------------
// Problem: x [16,48,207,512], 8 heads, d=64.  M = 158976 rows, K=N=512.
// ---------------------------------------------------------------------------
#define MB   16
#define TT   48
#define NV   207
#define FF   512
#define NHEAD 8
#define HD   64
#define MROWS (MB*TT*NV)          // 158976
#define SZ   ((size_t)MROWS * FF)

__device__ float g_scratch[6 * SZ];

// ---------------------------------------------------------------------------
// helpers
// ---------------------------------------------------------------------------
__device__ __forceinline__ void cp_async16(void* smem, const void* gmem) {
    unsigned s = (unsigned)__cvta_generic_to_shared(smem);
    asm volatile("cp.async.cg.shared.global [%0], [%1], 16;\n" :: "r"(s), "l"(gmem));
}
__device__ __forceinline__ void cp_commit() { asm volatile("cp.async.commit_group;\n" ::: "memory"); }
__device__ __forceinline__ void cp_wait0()  { asm volatile("cp.async.wait_group 0;\n" ::: "memory"); }

__device__ __forceinline__ void mma_bf16(float c[4], const uint32_t a[4], const uint32_t* b) {
    asm volatile(
        "mma.sync.aligned.m16n8k16.row.col.f32.bf16.bf16.f32 "
        "{%0,%1,%2,%3}, {%4,%5,%6,%7}, {%8,%9}, {%0,%1,%2,%3};\n"
        : "+f"(c[0]), "+f"(c[1]), "+f"(c[2]), "+f"(c[3])
        : "r"(a[0]), "r"(a[1]), "r"(a[2]), "r"(a[3]), "r"(b[0]), "r"(b[1]));
}
__device__ __forceinline__ void ldsm_x4(uint32_t r[4], uint32_t addr) {
    asm volatile("ldmatrix.sync.aligned.m8n8.x4.shared.b16 {%0,%1,%2,%3}, [%4];"
                 : "=r"(r[0]), "=r"(r[1]), "=r"(r[2]), "=r"(r[3]) : "r"(addr));
}

// ---------------------------------------------------------------------------
// bf16 HMMA GEMM: C = act(A[M,512] @ Bt^T + bias) (+resid)
//   CTA tile 64x128x64, 128 threads (4 warps in n), warp tile 64x32, ldmatrix,
//   2-stage cp.async pipeline, 4 CTAs/SM (measured-best config).
//   act: 0 bias->fp32 ; 1 bias+GELU->bf16 ; 2 bias+resid->fp32 ; 3 bias->bf16
// ---------------------------------------------------------------------------
#define BM 64
#define BN 128
#define BK 64
#define LDT 72
#define KDIM 512
#define KT (KDIM / BK)   // 8
#define A_BYTES (BM * LDT * 2)            // 9216
#define B_BYTES (BN * LDT * 2)            // 18432
#define GEMM_SMEM (2 * (A_BYTES + B_BYTES))   // 55296

__global__ __launch_bounds__(128, 4)
void gemm_bf16(const __nv_bfloat16* __restrict__ A,
               const __nv_bfloat16* __restrict__ Bt,
               const float* __restrict__ bias,
               const float* __restrict__ resid,
               void* __restrict__ C, int ldc, int act)
{
    extern __shared__ __align__(16) uint8_t dsm[];

    const int tid  = threadIdx.x;
    const int m0   = blockIdx.y * BM;
    const int n0   = blockIdx.x * BN;
    const int warp = tid >> 5;
    const int lane = tid & 31;
    const int wn   = warp * 32;
    const int g    = lane >> 2;
    const int t4   = lane & 3;

    uint8_t* As[2] = { dsm,                dsm + A_BYTES };
    uint8_t* Bs[2] = { dsm + 2 * A_BYTES,  dsm + 2 * A_BYTES + B_BYTES };
    const uint32_t sm_base = (uint32_t)__cvta_generic_to_shared(dsm);

    const int lr        = lane & 7;
    const int a_row_off = ((lane >> 3) & 1) * 8;
    const int a_col_off = (lane >> 4) * 8;
    const int b_row_off = (lane >> 4) * 8;
    const int b_col_off = ((lane >> 3) & 1) * 8;

    float c[4][4][4];
    #pragma unroll
    for (int i = 0; i < 4; i++)
        #pragma unroll
        for (int j = 0; j < 4; j++)
            #pragma unroll
            for (int r = 0; r < 4; r++) c[i][j][r] = 0.f;

    auto load_tiles = [&](int kt, int buf) {
        #pragma unroll
        for (int r = 0; r < 4; r++) {
            int ch  = tid + r * 128;
            int row = ch >> 3;
            int col = (ch & 7) * 8;
            cp_async16(As[buf] + row * (LDT * 2) + col * 2,
                       A + (size_t)(m0 + row) * KDIM + kt * BK + col);
        }
        #pragma unroll
        for (int r = 0; r < 8; r++) {
            int ch  = tid + r * 128;
            int row = ch >> 3;
            int col = (ch & 7) * 8;
            cp_async16(Bs[buf] + row * (LDT * 2) + col * 2,
                       Bt + (size_t)(n0 + row) * KDIM + kt * BK + col);
        }
    };

    load_tiles(0, 0);
    cp_commit();

    for (int kt = 0; kt < KT; kt++) {
        cp_wait0();
        __syncthreads();
        if (kt + 1 < KT) {
            load_tiles(kt + 1, (kt + 1) & 1);
            cp_commit();
        }
        const int buf = kt & 1;
        const uint32_t a_base = sm_base + buf * A_BYTES;
        const uint32_t b_base = sm_base + 2 * A_BYTES + buf * B_BYTES;

        #pragma unroll
        for (int kk = 0; kk < BK; kk += 16) {
            uint32_t af[4][4];
            #pragma unroll
            for (int i = 0; i < 4; i++)
                ldsm_x4(af[i], a_base +
                        ((i * 16 + lr + a_row_off) * LDT + kk + a_col_off) * 2);
            uint32_t bfr[2][4];
            #pragma unroll
            for (int jp = 0; jp < 2; jp++)
                ldsm_x4(bfr[jp], b_base +
                        ((wn + jp * 16 + lr + b_row_off) * LDT + kk + b_col_off) * 2);
            #pragma unroll
            for (int i = 0; i < 4; i++)
                #pragma unroll
                for (int j = 0; j < 4; j++)
                    mma_bf16(c[i][j], af[i], &bfr[j >> 1][(j & 1) * 2]);
        }
        // no trailing __syncthreads (2-stage rotation ordered by top barrier)
    }

    #pragma unroll
    for (int i = 0; i < 4; i++) {
        int row0 = m0 + i * 16 + g;
        int row1 = row0 + 8;
        #pragma unroll
        for (int j = 0; j < 4; j++) {
            int col = n0 + wn + j * 8 + 2 * t4;
            float b0 = bias[col], b1 = bias[col + 1];
            float v00 = c[i][j][0] + b0;
            float v01 = c[i][j][1] + b1;
            float v10 = c[i][j][2] + b0;
            float v11 = c[i][j][3] + b1;
            if (act == 1 || act == 3) {
                if (act == 1) {
                    v00 = 0.5f * v00 * (1.f + erff(v00 * 0.70710678118654752f));
                    v01 = 0.5f * v01 * (1.f + erff(v01 * 0.70710678118654752f));
                    v10 = 0.5f * v10 * (1.f + erff(v10 * 0.70710678118654752f));
                    v11 = 0.5f * v11 * (1.f + erff(v11 * 0.70710678118654752f));
                }
                __nv_bfloat16* Cb = (__nv_bfloat16*)C;
                *(__nv_bfloat162*)(Cb + (size_t)row0 * ldc + col) = __floats2bfloat162_rn(v00, v01);
                *(__nv_bfloat162*)(Cb + (size_t)row1 * ldc + col) = __floats2bfloat162_rn(v10, v11);
            } else {
                if (act == 2) {
                    const float* r0 = resid + (size_t)row0 * ldc + col;
                    const float* r1 = resid + (size_t)row1 * ldc + col;
                    v00 += r0[0]; v01 += r0[1];
                    v10 += r1[0]; v11 += r1[1];
                }
                float* Cf = (float*)C;
                *(float2*)(Cf + (size_t)row0 * ldc + col) = make_float2(v00, v01);
                *(float2*)(Cf + (size_t)row1 * ldc + col) = make_float2(v10, v11);
            }
        }
    }
}

// ---------------------------------------------------------------------------
// Attention: one block per (head, b, n).  HMMA tensor-core score and PV.
//   qs/ks raw bf16 (ldmatrix source), V stored transposed vt[j][s],
//   softmax emits bf16 P (masked entries exact 0), fp32 accum everywhere.
// ---------------------------------------------------------------------------
#define LDQB 36          // uints per qs/ks row: 144B
#define LDP  52          // fp32 score row stride
#define LDPB 56          // bf16 P row stride (elems): 112B
#define LDVT 56          // vt row stride (elems): 112B

__global__ __launch_bounds__(256, 4)
void attn_kernel(const __nv_bfloat16* __restrict__ qkv, __nv_bfloat16* __restrict__ o)
{
    __shared__ __align__(16) uint32_t qs[TT][LDQB];
    __shared__ __align__(16) uint32_t ks[TT][LDQB];
    __shared__ __align__(16) __nv_bfloat16 vt[HD][LDVT];   // V^T: [j][s]
    __shared__ __align__(16) float ps[TT][LDP];
    __shared__ __align__(16) __nv_bfloat16 pb[TT][LDPB];   // bf16 P

    const int bid = blockIdx.x;
    const int n   = bid % NV;
    const int b   = (bid / NV) % MB;
    const int h   = bid / (NV * MB);
    const int tid = threadIdx.x;

    const size_t brow  = (size_t)(b * TT) * NV + n;
    const size_t qbase = brow * 1536 + h * HD;
    const size_t tq    = (size_t)NV * 1536;

    // ---- load: raw 16B chunks; q/k straight, v scattered transposed ----
    for (int idx = tid; idx < 3 * TT * (HD / 8); idx += 256) {
        const int tens = idx / (TT * (HD / 8));
        const int c    = idx - tens * (TT * (HD / 8));
        const int t    = c >> 3;
        const int j4   = (c & 7) * 4;                 // uint offset in row
        const __nv_bfloat16* src = qkv + qbase + (size_t)t * tq + tens * 512 + j4 * 2;
        uint4 raw = *(const uint4*)src;
        if (tens == 0)      *(uint4*)&qs[t][j4] = raw;
        else if (tens == 1) *(uint4*)&ks[t][j4] = raw;
        else {
            const __nv_bfloat16* e = (const __nv_bfloat16*)&raw;
            const int j8 = j4 * 2;
            #pragma unroll
            for (int q = 0; q < 8; q++) vt[j8 + q][t] = e[q];
        }
    }
    __syncthreads();

    const int w    = tid >> 5;
    const int lane = tid & 31;
    const int lr        = lane & 7;
    const int a_row_off = ((lane >> 3) & 1) * 8;
    const int a_col_off = (lane >> 4) * 8;
    const int b_row_off = (lane >> 4) * 8;
    const int b_col_off = ((lane >> 3) & 1) * 8;
    const int g  = lane >> 2;
    const int t4 = lane & 3;

    const uint32_t qsb = (uint32_t)__cvta_generic_to_shared(&qs[0][0]);
    const uint32_t ksb = (uint32_t)__cvta_generic_to_shared(&ks[0][0]);
    const uint32_t vtb = (uint32_t)__cvta_generic_to_shared(&vt[0][0]);
    const uint32_t pbb = (uint32_t)__cvta_generic_to_shared(&pb[0][0]);

    // ---- score: S = Q.K^T via HMMA.  Warps 0..2, each 16 rows x 48 cols ----
    if (w < 3) {
        const int i0 = w * 16;
        float c[6][4];
        #pragma unroll
        for (int j = 0; j < 6; j++)
            #pragma unroll
            for (int r = 0; r < 4; r++) c[j][r] = 0.f;

        #pragma unroll
        for (int kk = 0; kk < HD; kk += 16) {
            uint32_t af[4];
            ldsm_x4(af, qsb + (i0 + lr + a_row_off) * 144 + (kk + a_col_off) * 2);
            uint32_t bfr[3][4];
            #pragma unroll
            for (int jp = 0; jp < 3; jp++)
                ldsm_x4(bfr[jp], ksb + (jp * 16 + lr + b_row_off) * 144 + (kk + b_col_off) * 2);
            #pragma unroll
            for (int j = 0; j < 6; j++)
                mma_bf16(c[j], af, &bfr[j >> 1][(j & 1) * 2]);
        }
        #pragma unroll
        for (int j = 0; j < 6; j++) {
            const int col = j * 8 + 2 * t4;
            *(float2*)&ps[i0 + g][col]     = make_float2(c[j][0] * 0.125f, c[j][1] * 0.125f);
            *(float2*)&ps[i0 + g + 8][col] = make_float2(c[j][2] * 0.125f, c[j][3] * 0.125f);
        }
    }
    __syncthreads();

    // ---- softmax: warp-per-row (8 warps x 6 rows) -> bf16 P, masked = 0 ----
    {
        #pragma unroll
        for (int r = 0; r < 6; r++) {
            const int i = w * 6 + r;
            float v0 = (lane <= i) ? ps[i][lane] : -1e30f;
            float v1 = (lane + 32 <= i) ? ps[i][lane + 32] : -1e30f;
            float mx = fmaxf(v0, v1);
            #pragma unroll
            for (int off = 16; off; off >>= 1)
                mx = fmaxf(mx, __shfl_xor_sync(0xFFFFFFFFu, mx, off));
            float e0 = (lane <= i)      ? __expf(v0 - mx) : 0.f;
            float e1 = (lane + 32 <= i) ? __expf(v1 - mx) : 0.f;
            float sum = e0 + e1;
            #pragma unroll
            for (int off = 16; off; off >>= 1)
                sum += __shfl_xor_sync(0xFFFFFFFFu, sum, off);
            float inv = 1.f / sum;
            pb[i][lane] = __float2bfloat16(e0 * inv);   // masked lanes: exact 0
            if (lane + 32 < TT) pb[i][lane + 32] = __float2bfloat16(e1 * inv);
        }
    }
    __syncthreads();

    // ---- PV: O = P.V via HMMA.  Warps 0..5, each 16 rows x 32 cols ----
    if (w < 6) {
        const int i0 = (w >> 1) * 16;
        const int c0 = (w & 1) * 32;
        float c[4][4];
        #pragma unroll
        for (int j = 0; j < 4; j++)
            #pragma unroll
            for (int r = 0; r < 4; r++) c[j][r] = 0.f;

        #pragma unroll
        for (int kk = 0; kk < TT; kk += 16) {
            uint32_t af[4];
            ldsm_x4(af, pbb + (i0 + lr + a_row_off) * (LDPB * 2) + (kk + a_col_off) * 2);
            uint32_t bfr[2][4];
            #pragma unroll
            for (int jp = 0; jp < 2; jp++)
                ldsm_x4(bfr[jp], vtb + (c0 + jp * 16 + lr + b_row_off) * (LDVT * 2)
                                     + (kk + b_col_off) * 2);
            #pragma unroll
            for (int j = 0; j < 4; j++)
                mma_bf16(c[j], af, &bfr[j >> 1][(j & 1) * 2]);
        }
        #pragma unroll
        for (int j = 0; j < 4; j++) {
            const int col = c0 + j * 8 + 2 * t4;
            const int r0 = i0 + g, r1 = r0 + 8;
            *(__nv_bfloat162*)(o + (brow + (size_t)r0 * NV) * FF + h * HD + col)
                = __floats2bfloat162_rn(c[j][0], c[j][1]);
            *(__nv_bfloat162*)(o + (brow + (size_t)r1 * NV) * FF + h * HD + col)
                = __floats2bfloat162_rn(c[j][2], c[j][3]);
        }
    }
}

// ---------------------------------------------------------------------------
// LayerNorm over last dim (512). One block (128 threads) per row.
// ---------------------------------------------------------------------------
__global__ __launch_bounds__(128)
void ln_kernel(const float* __restrict__ h, const float* __restrict__ gamma,
               const float* __restrict__ beta, float* __restrict__ out)
{
    __shared__ float red[8];
    const int row = blockIdx.x;
    const int tid = threadIdx.x;

    float4 val = ((const float4*)(h + (size_t)row * FF))[tid];
    float s  = val.x + val.y + val.z + val.w;
    float ss = val.x * val.x + val.y * val.y + val.z * val.z + val.w * val.w;
    #pragma unroll
    for (int off = 16; off; off >>= 1) {
        s  += __shfl_xor_sync(0xFFFFFFFFu, s,  off);
        ss += __shfl_xor_sync(0xFFFFFFFFu, ss, off);
    }
    if ((tid & 31) == 0) { red[tid >> 5] = s; red[4 + (tid >> 5)] = ss; }
    __syncthreads();
    s  = red[0] + red[1] + red[2] + red[3];
    ss = red[4] + red[5] + red[6] + red[7];

    float mean = s * (1.f / 512.f);
    float var  = ss * (1.f / 512.f) - mean * mean;
    float rstd = rsqrtf(var + 1e-5f);

    float4 gm = ((const float4*)gamma)[tid];
    float4 bt = ((const float4*)beta)[tid];
    float4 r;
    r.x = gm.x * (val.x - mean) * rstd + bt.x;
    r.y = gm.y * (val.y - mean) * rstd + bt.y;
    r.z = gm.z * (val.z - mean) * rstd + bt.z;
    r.w = gm.w * (val.w - mean) * rstd + bt.w;
    ((float4*)(out + (size_t)row * FF))[tid] = r;
}

// ---------------------------------------------------------------------------
// Prep kernels
// ---------------------------------------------------------------------------
__global__ void cvt_x_concat(const float* __restrict__ x, __nv_bfloat16* __restrict__ xb,
                             int n4,
                             const float* __restrict__ bq, const float* __restrict__ bk,
                             const float* __restrict__ bv, float* __restrict__ bqkv)
{
    int i = blockIdx.x * blockDim.x + threadIdx.x;
    if (i < n4) {
        float4 v = ((const float4*)x)[i];
        __nv_bfloat162* o = (__nv_bfloat162*)xb + (size_t)i * 2;
        o[0] = __floats2bfloat162_rn(v.x, v.y);
        o[1] = __floats2bfloat162_rn(v.z, v.w);
    }
    if (blockIdx.x == gridDim.x - 1) {
        for (int j = threadIdx.x; j < 1536; j += blockDim.x) {
            float v;
            if (j < 512)       v = bq[j];
            else if (j < 1024) v = bk[j - 512];
            else               v = bv[j - 1024];
            bqkv[j] = v;
        }
    }
}

__global__ void transp_set(const float* __restrict__ Wa, const float* __restrict__ Wb,
                           const float* __restrict__ Wc,
                           __nv_bfloat16* __restrict__ Ta,
                           __nv_bfloat16* __restrict__ Tb,
                           __nv_bfloat16* __restrict__ Tc)
{
    __shared__ float t[32][33];
    const float* W = (blockIdx.z == 0) ? Wa : (blockIdx.z == 1) ? Wb : Wc;
    __nv_bfloat16* Wt = (blockIdx.z == 0) ? Ta : (blockIdx.z == 1) ? Tb : Tc;
    if (W == nullptr) return;
    int bx = blockIdx.x * 32, by = blockIdx.y * 32;
    int tx = threadIdx.x, ty = threadIdx.y;
    #pragma unroll
    for (int r = 0; r < 32; r += 8)
        t[ty + r][tx] = W[(size_t)(by + ty + r) * 512 + bx + tx];
    __syncthreads();
    #pragma unroll
    for (int r = 0; r < 32; r += 8)
        Wt[(size_t)(bx + ty + r) * 512 + by + tx] = __float2bfloat16(t[tx][ty + r]);
}

// ---------------------------------------------------------------------------
// Launch
// ---------------------------------------------------------------------------
extern "C" void kernel_launch(void* const* d_in, const int* in_sizes, int n_in,
                              void* d_out, int out_size)
{
    const float* x     = (const float*)d_in[0];
    const float* Wq    = (const float*)d_in[1];
    const float* bq    = (const float*)d_in[2];
    const float* Wk    = (const float*)d_in[3];
    const float* bk    = (const float*)d_in[4];
    const float* Wv    = (const float*)d_in[5];
    const float* bv    = (const float*)d_in[6];
    const float* W1    = (const float*)d_in[7];
    const float* b1    = (const float*)d_in[8];
    const float* W2    = (const float*)d_in[9];
    const float* b2    = (const float*)d_in[10];
    const float* gamma = (const float*)d_in[11];
    const float* beta  = (const float*)d_in[12];
    float* out = (float*)d_out;

    float* s;
    cudaGetSymbolAddress((void**)&s, g_scratch);
    __nv_bfloat16*  qkvb  = (__nv_bfloat16*)s;                     // [M,1536] bf16
    float*          h2    = s + 3 * SZ;                            // [M,512]  fp32
    __nv_bfloat16*  xb    = (__nv_bfloat16*)(s + 4 * SZ);          // [M,512]  bf16
    __nv_bfloat16*  ob    = (__nv_bfloat16*)(s + 4 * SZ + SZ / 2); // [M,512]  bf16
    __nv_bfloat16*  h1b   = (__nv_bfloat16*)(s + 5 * SZ);          // [M,512]  bf16
    __nv_bfloat16*  wqkvT = (__nv_bfloat16*)(s + 5 * SZ + SZ / 2); // [1536,512] bf16
    __nv_bfloat16*  w1T   = wqkvT + (size_t)1536 * 512;
    __nv_bfloat16*  w2T   = w1T   + (size_t)512 * 512;
    float*          bqkv  = (float*)(w2T + (size_t)512 * 512);     // [1536]

    cudaFuncSetAttribute(gemm_bf16, cudaFuncAttributeMaxDynamicSharedMemorySize, GEMM_SMEM);

    // prep (2 launches before QKV)
    cvt_x_concat<<<(int)((SZ / 4 + 255) / 256), 256>>>(
        x, xb, (int)(SZ / 4), bq, bk, bv, bqkv);
    transp_set<<<dim3(16, 16, 3), dim3(32, 8)>>>(
        Wq, Wk, Wv,
        wqkvT, wqkvT + (size_t)512 * 512, wqkvT + (size_t)1024 * 512);

    // fused QKV GEMM -> bf16 qkv
    gemm_bf16<<<dim3(1536 / BN, MROWS / BM), 128, GEMM_SMEM>>>(
        xb, wqkvT, bqkv, nullptr, qkvb, 1536, 3);

    attn_kernel<<<NHEAD * MB * NV, 256>>>(qkvb, ob);

    // W1/W2 transpose deferred (only needed by FFN1/FFN2)
    transp_set<<<dim3(16, 16, 2), dim3(32, 8)>>>(
        W1, W2, nullptr, w1T, w2T, nullptr);

    // FFN1 (+GELU -> bf16)
    gemm_bf16<<<dim3(FF / BN, MROWS / BM), 128, GEMM_SMEM>>>(
        ob, w1T, b1, nullptr, h1b, FF, 1);
    // FFN2 (+bias +residual -> fp32)
    gemm_bf16<<<dim3(FF / BN, MROWS / BM), 128, GEMM_SMEM>>>(
        h1b, w2T, b2, x, h2, FF, 2);

    ln_kernel<<<MROWS, 128>>>(h2, gamma, beta, out);
}

// round 16
// speedup vs baseline: 1.2448x; 1.0383x over previous
#include <cuda_runtime.h>
#include <cuda_bf16.h>
#include <math.h>
#include <stdint.h>

// ---------------------------------------------------------------------------
// Problem: x [16,48,207,512], 8 heads, d=64.  M = 158976 rows, K=N=512.
// ---------------------------------------------------------------------------
#define MB   16
#define TT   48
#define NV   207
#define FF   512
#define NHEAD 8
#define HD   64
#define MROWS (MB*TT*NV)          // 158976
#define SZ   ((size_t)MROWS * FF)

__device__ float g_scratch[6 * SZ];

// ---------------------------------------------------------------------------
// helpers
// ---------------------------------------------------------------------------
__device__ __forceinline__ void cp_async16(void* smem, const void* gmem) {
    unsigned s = (unsigned)__cvta_generic_to_shared(smem);
    asm volatile("cp.async.cg.shared.global [%0], [%1], 16;\n" :: "r"(s), "l"(gmem));
}
__device__ __forceinline__ void cp_commit() { asm volatile("cp.async.commit_group;\n" ::: "memory"); }
__device__ __forceinline__ void cp_wait0()  { asm volatile("cp.async.wait_group 0;\n" ::: "memory"); }

__device__ __forceinline__ void mma_bf16(float c[4], const uint32_t a[4], const uint32_t* b) {
    asm volatile(
        "mma.sync.aligned.m16n8k16.row.col.f32.bf16.bf16.f32 "
        "{%0,%1,%2,%3}, {%4,%5,%6,%7}, {%8,%9}, {%0,%1,%2,%3};\n"
        : "+f"(c[0]), "+f"(c[1]), "+f"(c[2]), "+f"(c[3])
        : "r"(a[0]), "r"(a[1]), "r"(a[2]), "r"(a[3]), "r"(b[0]), "r"(b[1]));
}
__device__ __forceinline__ void ldsm_x4(uint32_t r[4], uint32_t addr) {
    asm volatile("ldmatrix.sync.aligned.m8n8.x4.shared.b16 {%0,%1,%2,%3}, [%4];"
                 : "=r"(r[0]), "=r"(r[1]), "=r"(r[2]), "=r"(r[3]) : "r"(addr));
}

// ---------------------------------------------------------------------------
// bf16 HMMA GEMM: C = act(A[M,512] @ Bt^T + bias) (+resid)
//   CTA tile 64x128x64, 128 threads (4 warps in n), warp tile 64x32, ldmatrix,
//   2-stage cp.async pipeline, 4 CTAs/SM (measured-best config).
//   act: 0 bias->fp32 ; 1 bias+GELU->bf16 ; 2 bias+resid->fp32 ; 3 bias->bf16
// ---------------------------------------------------------------------------
#define BM 64
#define BN 128
#define BK 64
#define LDT 72
#define KDIM 512
#define KT (KDIM / BK)   // 8
#define A_BYTES (BM * LDT * 2)            // 9216
#define B_BYTES (BN * LDT * 2)            // 18432
#define GEMM_SMEM (2 * (A_BYTES + B_BYTES))   // 55296

__global__ __launch_bounds__(128, 4)
void gemm_bf16(const __nv_bfloat16* __restrict__ A,
               const __nv_bfloat16* __restrict__ Bt,
               const float* __restrict__ bias,
               const float* __restrict__ resid,
               void* __restrict__ C, int ldc, int act)
{
    extern __shared__ __align__(16) uint8_t dsm[];

    const int tid  = threadIdx.x;
    const int m0   = blockIdx.y * BM;
    const int n0   = blockIdx.x * BN;
    const int warp = tid >> 5;
    const int lane = tid & 31;
    const int wn   = warp * 32;
    const int g    = lane >> 2;
    const int t4   = lane & 3;

    uint8_t* As[2] = { dsm,                dsm + A_BYTES };
    uint8_t* Bs[2] = { dsm + 2 * A_BYTES,  dsm + 2 * A_BYTES + B_BYTES };
    const uint32_t sm_base = (uint32_t)__cvta_generic_to_shared(dsm);

    const int lr        = lane & 7;
    const int a_row_off = ((lane >> 3) & 1) * 8;
    const int a_col_off = (lane >> 4) * 8;
    const int b_row_off = (lane >> 4) * 8;
    const int b_col_off = ((lane >> 3) & 1) * 8;

    float c[4][4][4];
    #pragma unroll
    for (int i = 0; i < 4; i++)
        #pragma unroll
        for (int j = 0; j < 4; j++)
            #pragma unroll
            for (int r = 0; r < 4; r++) c[i][j][r] = 0.f;

    auto load_tiles = [&](int kt, int buf) {
        #pragma unroll
        for (int r = 0; r < 4; r++) {
            int ch  = tid + r * 128;
            int row = ch >> 3;
            int col = (ch & 7) * 8;
            cp_async16(As[buf] + row * (LDT * 2) + col * 2,
                       A + (size_t)(m0 + row) * KDIM + kt * BK + col);
        }
        #pragma unroll
        for (int r = 0; r < 8; r++) {
            int ch  = tid + r * 128;
            int row = ch >> 3;
            int col = (ch & 7) * 8;
            cp_async16(Bs[buf] + row * (LDT * 2) + col * 2,
                       Bt + (size_t)(n0 + row) * KDIM + kt * BK + col);
        }
    };

    load_tiles(0, 0);
    cp_commit();

    for (int kt = 0; kt < KT; kt++) {
        cp_wait0();
        __syncthreads();
        if (kt + 1 < KT) {
            load_tiles(kt + 1, (kt + 1) & 1);
            cp_commit();
        }
        const int buf = kt & 1;
        const uint32_t a_base = sm_base + buf * A_BYTES;
        const uint32_t b_base = sm_base + 2 * A_BYTES + buf * B_BYTES;

        #pragma unroll
        for (int kk = 0; kk < BK; kk += 16) {
            uint32_t af[4][4];
            #pragma unroll
            for (int i = 0; i < 4; i++)
                ldsm_x4(af[i], a_base +
                        ((i * 16 + lr + a_row_off) * LDT + kk + a_col_off) * 2);
            uint32_t bfr[2][4];
            #pragma unroll
            for (int jp = 0; jp < 2; jp++)
                ldsm_x4(bfr[jp], b_base +
                        ((wn + jp * 16 + lr + b_row_off) * LDT + kk + b_col_off) * 2);
            #pragma unroll
            for (int i = 0; i < 4; i++)
                #pragma unroll
                for (int j = 0; j < 4; j++)
                    mma_bf16(c[i][j], af[i], &bfr[j >> 1][(j & 1) * 2]);
        }
        // no trailing __syncthreads (2-stage rotation ordered by top barrier)
    }

    #pragma unroll
    for (int i = 0; i < 4; i++) {
        int row0 = m0 + i * 16 + g;
        int row1 = row0 + 8;
        #pragma unroll
        for (int j = 0; j < 4; j++) {
            int col = n0 + wn + j * 8 + 2 * t4;
            float b0 = bias[col], b1 = bias[col + 1];
            float v00 = c[i][j][0] + b0;
            float v01 = c[i][j][1] + b1;
            float v10 = c[i][j][2] + b0;
            float v11 = c[i][j][3] + b1;
            if (act == 1 || act == 3) {
                if (act == 1) {
                    v00 = 0.5f * v00 * (1.f + erff(v00 * 0.70710678118654752f));
                    v01 = 0.5f * v01 * (1.f + erff(v01 * 0.70710678118654752f));
                    v10 = 0.5f * v10 * (1.f + erff(v10 * 0.70710678118654752f));
                    v11 = 0.5f * v11 * (1.f + erff(v11 * 0.70710678118654752f));
                }
                __nv_bfloat16* Cb = (__nv_bfloat16*)C;
                *(__nv_bfloat162*)(Cb + (size_t)row0 * ldc + col) = __floats2bfloat162_rn(v00, v01);
                *(__nv_bfloat162*)(Cb + (size_t)row1 * ldc + col) = __floats2bfloat162_rn(v10, v11);
            } else {
                if (act == 2) {
                    const float* r0 = resid + (size_t)row0 * ldc + col;
                    const float* r1 = resid + (size_t)row1 * ldc + col;
                    v00 += r0[0]; v01 += r0[1];
                    v10 += r1[0]; v11 += r1[1];
                }
                float* Cf = (float*)C;
                *(float2*)(Cf + (size_t)row0 * ldc + col) = make_float2(v00, v01);
                *(float2*)(Cf + (size_t)row1 * ldc + col) = make_float2(v10, v11);
            }
        }
    }
}

// ---------------------------------------------------------------------------
// Attention: one block per (head, b, n).  HMMA score/PV with EXACT causal
// truncation of tile work; cp.async q/k loads; bf16 P; fp32 accum.
// ---------------------------------------------------------------------------
#define LDQB 36          // uints per qs/ks row: 144B
#define LDP  52          // fp32 score row stride
#define LDPB 56          // bf16 P row stride (elems): 112B
#define LDVT 56          // vt row stride (elems): 112B

__global__ __launch_bounds__(256, 4)
void attn_kernel(const __nv_bfloat16* __restrict__ qkv, __nv_bfloat16* __restrict__ o)
{
    __shared__ __align__(16) uint32_t qs[TT][LDQB];
    __shared__ __align__(16) uint32_t ks[TT][LDQB];
    __shared__ __align__(16) __nv_bfloat16 vt[HD][LDVT];   // V^T: [j][s]
    __shared__ __align__(16) float ps[TT][LDP];
    __shared__ __align__(16) __nv_bfloat16 pb[TT][LDPB];   // bf16 P

    const int bid = blockIdx.x;
    const int n   = bid % NV;
    const int b   = (bid / NV) % MB;
    const int h   = bid / (NV * MB);
    const int tid = threadIdx.x;

    const size_t brow  = (size_t)(b * TT) * NV + n;
    const size_t qbase = brow * 1536 + h * HD;
    const size_t tq    = (size_t)NV * 1536;

    // ---- load: q/k via cp.async (768 chunks), v via LDG + transpose scatter ----
    for (int idx = tid; idx < 2 * TT * (HD / 8); idx += 256) {
        const int tens = idx / (TT * (HD / 8));      // 0=q, 1=k
        const int c    = idx - tens * (TT * (HD / 8));
        const int t    = c >> 3;
        const int j4   = (c & 7) * 4;
        const __nv_bfloat16* src = qkv + qbase + (size_t)t * tq + tens * 512 + j4 * 2;
        void* dst = (tens == 0) ? (void*)&qs[t][j4] : (void*)&ks[t][j4];
        cp_async16(dst, src);
    }
    cp_commit();
    for (int idx = tid; idx < TT * (HD / 8); idx += 256) {
        const int t  = idx >> 3;
        const int j4 = (idx & 7) * 4;
        const __nv_bfloat16* src = qkv + qbase + (size_t)t * tq + 1024 + j4 * 2;
        uint4 raw = *(const uint4*)src;
        const __nv_bfloat16* e = (const __nv_bfloat16*)&raw;
        const int j8 = j4 * 2;
        #pragma unroll
        for (int q = 0; q < 8; q++) vt[j8 + q][t] = e[q];
    }
    cp_wait0();
    __syncthreads();

    const int w    = tid >> 5;
    const int lane = tid & 31;
    const int lr        = lane & 7;
    const int a_row_off = ((lane >> 3) & 1) * 8;
    const int a_col_off = (lane >> 4) * 8;
    const int b_row_off = (lane >> 4) * 8;
    const int b_col_off = ((lane >> 3) & 1) * 8;
    const int g  = lane >> 2;
    const int t4 = lane & 3;

    const uint32_t qsb = (uint32_t)__cvta_generic_to_shared(&qs[0][0]);
    const uint32_t ksb = (uint32_t)__cvta_generic_to_shared(&ks[0][0]);
    const uint32_t vtb = (uint32_t)__cvta_generic_to_shared(&vt[0][0]);
    const uint32_t pbb = (uint32_t)__cvta_generic_to_shared(&pb[0][0]);

    // ---- score: S = Q.K^T via HMMA.  Warp w: rows 16w..16w+15, causal-
    //      truncated to column tiles j < 2(w+1) (cols beyond are never read).
    if (w < 3) {
        const int i0   = w * 16;
        const int jmax = 2 * (w + 1);
        float c[6][4];
        #pragma unroll
        for (int j = 0; j < 6; j++)
            #pragma unroll
            for (int r = 0; r < 4; r++) c[j][r] = 0.f;

        #pragma unroll
        for (int kk = 0; kk < HD; kk += 16) {
            uint32_t af[4];
            ldsm_x4(af, qsb + (i0 + lr + a_row_off) * 144 + (kk + a_col_off) * 2);
            uint32_t bfr[3][4];
            #pragma unroll
            for (int jp = 0; jp < 3; jp++)
                if (jp < (jmax >> 1))
                    ldsm_x4(bfr[jp], ksb + (jp * 16 + lr + b_row_off) * 144
                                         + (kk + b_col_off) * 2);
            #pragma unroll
            for (int j = 0; j < 6; j++)
                if (j < jmax)
                    mma_bf16(c[j], af, &bfr[j >> 1][(j & 1) * 2]);
        }
        #pragma unroll
        for (int j = 0; j < 6; j++)
            if (j < jmax) {
                const int col = j * 8 + 2 * t4;
                *(float2*)&ps[i0 + g][col]     = make_float2(c[j][0] * 0.125f, c[j][1] * 0.125f);
                *(float2*)&ps[i0 + g + 8][col] = make_float2(c[j][2] * 0.125f, c[j][3] * 0.125f);
            }
    }
    __syncthreads();

    // ---- softmax: warp-per-row (8 warps x 6 rows) -> bf16 P, masked = 0 ----
    {
        #pragma unroll
        for (int r = 0; r < 6; r++) {
            const int i = w * 6 + r;
            float v0 = (lane <= i) ? ps[i][lane] : -1e30f;
            float v1 = (lane + 32 <= i) ? ps[i][lane + 32] : -1e30f;
            float mx = fmaxf(v0, v1);
            #pragma unroll
            for (int off = 16; off; off >>= 1)
                mx = fmaxf(mx, __shfl_xor_sync(0xFFFFFFFFu, mx, off));
            float e0 = (lane <= i)      ? __expf(v0 - mx) : 0.f;
            float e1 = (lane + 32 <= i) ? __expf(v1 - mx) : 0.f;
            float sum = e0 + e1;
            #pragma unroll
            for (int off = 16; off; off >>= 1)
                sum += __shfl_xor_sync(0xFFFFFFFFu, sum, off);
            float inv = 1.f / sum;
            pb[i][lane] = __float2bfloat16(e0 * inv);   // masked lanes: exact 0
            if (lane + 32 < TT) pb[i][lane + 32] = __float2bfloat16(e1 * inv);
        }
    }
    __syncthreads();

    // ---- PV: O = P.V via HMMA.  Warp pair (rows i0): k-tiles truncated to
    //      (i0/16)+1 (P is exactly 0 beyond the causal boundary).
    if (w < 6) {
        const int i0   = (w >> 1) * 16;
        const int c0   = (w & 1) * 32;
        const int kmax = ((w >> 1) + 1) * 16;
        float c[4][4];
        #pragma unroll
        for (int j = 0; j < 4; j++)
            #pragma unroll
            for (int r = 0; r < 4; r++) c[j][r] = 0.f;

        #pragma unroll
        for (int kk = 0; kk < TT; kk += 16)
            if (kk < kmax) {
                uint32_t af[4];
                ldsm_x4(af, pbb + (i0 + lr + a_row_off) * (LDPB * 2) + (kk + a_col_off) * 2);
                uint32_t bfr[2][4];
                #pragma unroll
                for (int jp = 0; jp < 2; jp++)
                    ldsm_x4(bfr[jp], vtb + (c0 + jp * 16 + lr + b_row_off) * (LDVT * 2)
                                         + (kk + b_col_off) * 2);
                #pragma unroll
                for (int j = 0; j < 4; j++)
                    mma_bf16(c[j], af, &bfr[j >> 1][(j & 1) * 2]);
            }
        #pragma unroll
        for (int j = 0; j < 4; j++) {
            const int col = c0 + j * 8 + 2 * t4;
            const int r0 = i0 + g, r1 = r0 + 8;
            *(__nv_bfloat162*)(o + (brow + (size_t)r0 * NV) * FF + h * HD + col)
                = __floats2bfloat162_rn(c[j][0], c[j][1]);
            *(__nv_bfloat162*)(o + (brow + (size_t)r1 * NV) * FF + h * HD + col)
                = __floats2bfloat162_rn(c[j][2], c[j][3]);
        }
    }
}

// ---------------------------------------------------------------------------
// LayerNorm over last dim (512). One block (128 threads) per row.
// ---------------------------------------------------------------------------
__global__ __launch_bounds__(128)
void ln_kernel(const float* __restrict__ h, const float* __restrict__ gamma,
               const float* __restrict__ beta, float* __restrict__ out)
{
    __shared__ float red[8];
    const int row = blockIdx.x;
    const int tid = threadIdx.x;

    float4 val = ((const float4*)(h + (size_t)row * FF))[tid];
    float s  = val.x + val.y + val.z + val.w;
    float ss = val.x * val.x + val.y * val.y + val.z * val.z + val.w * val.w;
    #pragma unroll
    for (int off = 16; off; off >>= 1) {
        s  += __shfl_xor_sync(0xFFFFFFFFu, s,  off);
        ss += __shfl_xor_sync(0xFFFFFFFFu, ss, off);
    }
    if ((tid & 31) == 0) { red[tid >> 5] = s; red[4 + (tid >> 5)] = ss; }
    __syncthreads();
    s  = red[0] + red[1] + red[2] + red[3];
    ss = red[4] + red[5] + red[6] + red[7];

    float mean = s * (1.f / 512.f);
    float var  = ss * (1.f / 512.f) - mean * mean;
    float rstd = rsqrtf(var + 1e-5f);

    float4 gm = ((const float4*)gamma)[tid];
    float4 bt = ((const float4*)beta)[tid];
    float4 r;
    r.x = gm.x * (val.x - mean) * rstd + bt.x;
    r.y = gm.y * (val.y - mean) * rstd + bt.y;
    r.z = gm.z * (val.z - mean) * rstd + bt.z;
    r.w = gm.w * (val.w - mean) * rstd + bt.w;
    ((float4*)(out + (size_t)row * FF))[tid] = r;
}

// ---------------------------------------------------------------------------
// Prep kernels
// ---------------------------------------------------------------------------
__global__ void cvt_x_concat(const float* __restrict__ x, __nv_bfloat16* __restrict__ xb,
                             int n4,
                             const float* __restrict__ bq, const float* __restrict__ bk,
                             const float* __restrict__ bv, float* __restrict__ bqkv)
{
    int i = blockIdx.x * blockDim.x + threadIdx.x;
    if (i < n4) {
        float4 v = ((const float4*)x)[i];
        __nv_bfloat162* o = (__nv_bfloat162*)xb + (size_t)i * 2;
        o[0] = __floats2bfloat162_rn(v.x, v.y);
        o[1] = __floats2bfloat162_rn(v.z, v.w);
    }
    if (blockIdx.x == gridDim.x - 1) {
        for (int j = threadIdx.x; j < 1536; j += blockDim.x) {
            float v;
            if (j < 512)       v = bq[j];
            else if (j < 1024) v = bk[j - 512];
            else               v = bv[j - 1024];
            bqkv[j] = v;
        }
    }
}

__global__ void transp_set(const float* __restrict__ Wa, const float* __restrict__ Wb,
                           const float* __restrict__ Wc,
                           __nv_bfloat16* __restrict__ Ta,
                           __nv_bfloat16* __restrict__ Tb,
                           __nv_bfloat16* __restrict__ Tc)
{
    __shared__ float t[32][33];
    const float* W = (blockIdx.z == 0) ? Wa : (blockIdx.z == 1) ? Wb : Wc;
    __nv_bfloat16* Wt = (blockIdx.z == 0) ? Ta : (blockIdx.z == 1) ? Tb : Tc;
    if (W == nullptr) return;
    int bx = blockIdx.x * 32, by = blockIdx.y * 32;
    int tx = threadIdx.x, ty = threadIdx.y;
    #pragma unroll
    for (int r = 0; r < 32; r += 8)
        t[ty + r][tx] = W[(size_t)(by + ty + r) * 512 + bx + tx];
    __syncthreads();
    #pragma unroll
    for (int r = 0; r < 32; r += 8)
        Wt[(size_t)(bx + ty + r) * 512 + by + tx] = __float2bfloat16(t[tx][ty + r]);
}

// ---------------------------------------------------------------------------
// Launch
// ---------------------------------------------------------------------------
extern "C" void kernel_launch(void* const* d_in, const int* in_sizes, int n_in,
                              void* d_out, int out_size)
{
    const float* x     = (const float*)d_in[0];
    const float* Wq    = (const float*)d_in[1];
    const float* bq    = (const float*)d_in[2];
    const float* Wk    = (const float*)d_in[3];
    const float* bk    = (const float*)d_in[4];
    const float* Wv    = (const float*)d_in[5];
    const float* bv    = (const float*)d_in[6];
    const float* W1    = (const float*)d_in[7];
    const float* b1    = (const float*)d_in[8];
    const float* W2    = (const float*)d_in[9];
    const float* b2    = (const float*)d_in[10];
    const float* gamma = (const float*)d_in[11];
    const float* beta  = (const float*)d_in[12];
    float* out = (float*)d_out;

    float* s;
    cudaGetSymbolAddress((void**)&s, g_scratch);
    __nv_bfloat16*  qkvb  = (__nv_bfloat16*)s;                     // [M,1536] bf16
    float*          h2    = s + 3 * SZ;                            // [M,512]  fp32
    __nv_bfloat16*  xb    = (__nv_bfloat16*)(s + 4 * SZ);          // [M,512]  bf16
    __nv_bfloat16*  ob    = (__nv_bfloat16*)(s + 4 * SZ + SZ / 2); // [M,512]  bf16
    __nv_bfloat16*  h1b   = (__nv_bfloat16*)(s + 5 * SZ);          // [M,512]  bf16
    __nv_bfloat16*  wqkvT = (__nv_bfloat16*)(s + 5 * SZ + SZ / 2); // [1536,512] bf16
    __nv_bfloat16*  w1T   = wqkvT + (size_t)1536 * 512;
    __nv_bfloat16*  w2T   = w1T   + (size_t)512 * 512;
    float*          bqkv  = (float*)(w2T + (size_t)512 * 512);     // [1536]

    cudaFuncSetAttribute(gemm_bf16, cudaFuncAttributeMaxDynamicSharedMemorySize, GEMM_SMEM);

    // prep (2 launches before QKV)
    cvt_x_concat<<<(int)((SZ / 4 + 255) / 256), 256>>>(
        x, xb, (int)(SZ / 4), bq, bk, bv, bqkv);
    transp_set<<<dim3(16, 16, 3), dim3(32, 8)>>>(
        Wq, Wk, Wv,
        wqkvT, wqkvT + (size_t)512 * 512, wqkvT + (size_t)1024 * 512);

    // fused QKV GEMM -> bf16 qkv
    gemm_bf16<<<dim3(1536 / BN, MROWS / BM), 128, GEMM_SMEM>>>(
        xb, wqkvT, bqkv, nullptr, qkvb, 1536, 3);

    attn_kernel<<<NHEAD * MB * NV, 256>>>(qkvb, ob);

    // W1/W2 transpose deferred (only needed by FFN1/FFN2)
    transp_set<<<dim3(16, 16, 2), dim3(32, 8)>>>(
        W1, W2, nullptr, w1T, w2T, nullptr);

    // FFN1 (+GELU -> bf16)
    gemm_bf16<<<dim3(FF / BN, MROWS / BM), 128, GEMM_SMEM>>>(
        ob, w1T, b1, nullptr, h1b, FF, 1);
    // FFN2 (+bias +residual -> fp32)
    gemm_bf16<<<dim3(FF / BN, MROWS / BM), 128, GEMM_SMEM>>>(
        h1b, w2T, b2, x, h2, FF, 2);

    ln_kernel<<<MROWS, 128>>>(h2, gamma, beta, out);
}

// round 17
// speedup vs baseline: 1.2548x; 1.0081x over previous
#include <cuda_runtime.h>
#include <cuda_bf16.h>
#include <math.h>
#include <stdint.h>

// ---------------------------------------------------------------------------
// Problem: x [16,48,207,512], 8 heads, d=64.  M = 158976 rows, K=N=512.
// ---------------------------------------------------------------------------
#define MB   16
#define TT   48
#define NV   207
#define FF   512
#define NHEAD 8
#define HD   64
#define MROWS (MB*TT*NV)          // 158976
#define SZ   ((size_t)MROWS * FF)

__device__ float g_scratch[6 * SZ];

// ---------------------------------------------------------------------------
// helpers
// ---------------------------------------------------------------------------
__device__ __forceinline__ void cp_async16(void* smem, const void* gmem) {
    unsigned s = (unsigned)__cvta_generic_to_shared(smem);
    asm volatile("cp.async.cg.shared.global [%0], [%1], 16;\n" :: "r"(s), "l"(gmem));
}
__device__ __forceinline__ void cp_commit() { asm volatile("cp.async.commit_group;\n" ::: "memory"); }
__device__ __forceinline__ void cp_wait0()  { asm volatile("cp.async.wait_group 0;\n" ::: "memory"); }

__device__ __forceinline__ void mma_bf16(float c[4], const uint32_t a[4], const uint32_t* b) {
    asm volatile(
        "mma.sync.aligned.m16n8k16.row.col.f32.bf16.bf16.f32 "
        "{%0,%1,%2,%3}, {%4,%5,%6,%7}, {%8,%9}, {%0,%1,%2,%3};\n"
        : "+f"(c[0]), "+f"(c[1]), "+f"(c[2]), "+f"(c[3])
        : "r"(a[0]), "r"(a[1]), "r"(a[2]), "r"(a[3]), "r"(b[0]), "r"(b[1]));
}
__device__ __forceinline__ void ldsm_x4(uint32_t r[4], uint32_t addr) {
    asm volatile("ldmatrix.sync.aligned.m8n8.x4.shared.b16 {%0,%1,%2,%3}, [%4];"
                 : "=r"(r[0]), "=r"(r[1]), "=r"(r[2]), "=r"(r[3]) : "r"(addr));
}

// ---------------------------------------------------------------------------
// bf16 HMMA GEMM: C = act(A[M,512] @ Bt^T + bias) (+resid)
//   CTA tile 64x128x64, 128 threads (4 warps in n), warp tile 64x32, ldmatrix,
//   2-stage cp.async pipeline, 4 CTAs/SM (measured-best config).
//   act: 0 bias->fp32 ; 1 bias+GELU->bf16 ; 2 bias+resid->fp32 ; 3 bias->bf16
// ---------------------------------------------------------------------------
#define BM 64
#define BN 128
#define BK 64
#define LDT 72
#define KDIM 512
#define KT (KDIM / BK)   // 8
#define A_BYTES (BM * LDT * 2)            // 9216
#define B_BYTES (BN * LDT * 2)            // 18432
#define GEMM_SMEM (2 * (A_BYTES + B_BYTES))   // 55296

__global__ __launch_bounds__(128, 4)
void gemm_bf16(const __nv_bfloat16* __restrict__ A,
               const __nv_bfloat16* __restrict__ Bt,
               const float* __restrict__ bias,
               const float* __restrict__ resid,
               void* __restrict__ C, int ldc, int act)
{
    extern __shared__ __align__(16) uint8_t dsm[];

    const int tid  = threadIdx.x;
    const int m0   = blockIdx.y * BM;
    const int n0   = blockIdx.x * BN;
    const int warp = tid >> 5;
    const int lane = tid & 31;
    const int wn   = warp * 32;
    const int g    = lane >> 2;
    const int t4   = lane & 3;

    uint8_t* As[2] = { dsm,                dsm + A_BYTES };
    uint8_t* Bs[2] = { dsm + 2 * A_BYTES,  dsm + 2 * A_BYTES + B_BYTES };
    const uint32_t sm_base = (uint32_t)__cvta_generic_to_shared(dsm);

    const int lr        = lane & 7;
    const int a_row_off = ((lane >> 3) & 1) * 8;
    const int a_col_off = (lane >> 4) * 8;
    const int b_row_off = (lane >> 4) * 8;
    const int b_col_off = ((lane >> 3) & 1) * 8;

    float c[4][4][4];
    #pragma unroll
    for (int i = 0; i < 4; i++)
        #pragma unroll
        for (int j = 0; j < 4; j++)
            #pragma unroll
            for (int r = 0; r < 4; r++) c[i][j][r] = 0.f;

    auto load_tiles = [&](int kt, int buf) {
        #pragma unroll
        for (int r = 0; r < 4; r++) {
            int ch  = tid + r * 128;
            int row = ch >> 3;
            int col = (ch & 7) * 8;
            cp_async16(As[buf] + row * (LDT * 2) + col * 2,
                       A + (size_t)(m0 + row) * KDIM + kt * BK + col);
        }
        #pragma unroll
        for (int r = 0; r < 8; r++) {
            int ch  = tid + r * 128;
            int row = ch >> 3;
            int col = (ch & 7) * 8;
            cp_async16(Bs[buf] + row * (LDT * 2) + col * 2,
                       Bt + (size_t)(n0 + row) * KDIM + kt * BK + col);
        }
    };

    load_tiles(0, 0);
    cp_commit();

    for (int kt = 0; kt < KT; kt++) {
        cp_wait0();
        __syncthreads();
        if (kt + 1 < KT) {
            load_tiles(kt + 1, (kt + 1) & 1);
            cp_commit();
        }
        const int buf = kt & 1;
        const uint32_t a_base = sm_base + buf * A_BYTES;
        const uint32_t b_base = sm_base + 2 * A_BYTES + buf * B_BYTES;

        #pragma unroll
        for (int kk = 0; kk < BK; kk += 16) {
            uint32_t af[4][4];
            #pragma unroll
            for (int i = 0; i < 4; i++)
                ldsm_x4(af[i], a_base +
                        ((i * 16 + lr + a_row_off) * LDT + kk + a_col_off) * 2);
            uint32_t bfr[2][4];
            #pragma unroll
            for (int jp = 0; jp < 2; jp++)
                ldsm_x4(bfr[jp], b_base +
                        ((wn + jp * 16 + lr + b_row_off) * LDT + kk + b_col_off) * 2);
            #pragma unroll
            for (int i = 0; i < 4; i++)
                #pragma unroll
                for (int j = 0; j < 4; j++)
                    mma_bf16(c[i][j], af[i], &bfr[j >> 1][(j & 1) * 2]);
        }
        // no trailing __syncthreads (2-stage rotation ordered by top barrier)
    }

    #pragma unroll
    for (int i = 0; i < 4; i++) {
        int row0 = m0 + i * 16 + g;
        int row1 = row0 + 8;
        #pragma unroll
        for (int j = 0; j < 4; j++) {
            int col = n0 + wn + j * 8 + 2 * t4;
            float b0 = bias[col], b1 = bias[col + 1];
            float v00 = c[i][j][0] + b0;
            float v01 = c[i][j][1] + b1;
            float v10 = c[i][j][2] + b0;
            float v11 = c[i][j][3] + b1;
            if (act == 1 || act == 3) {
                if (act == 1) {
                    v00 = 0.5f * v00 * (1.f + erff(v00 * 0.70710678118654752f));
                    v01 = 0.5f * v01 * (1.f + erff(v01 * 0.70710678118654752f));
                    v10 = 0.5f * v10 * (1.f + erff(v10 * 0.70710678118654752f));
                    v11 = 0.5f * v11 * (1.f + erff(v11 * 0.70710678118654752f));
                }
                __nv_bfloat16* Cb = (__nv_bfloat16*)C;
                *(__nv_bfloat162*)(Cb + (size_t)row0 * ldc + col) = __floats2bfloat162_rn(v00, v01);
                *(__nv_bfloat162*)(Cb + (size_t)row1 * ldc + col) = __floats2bfloat162_rn(v10, v11);
            } else {
                if (act == 2) {
                    const float* r0 = resid + (size_t)row0 * ldc + col;
                    const float* r1 = resid + (size_t)row1 * ldc + col;
                    v00 += r0[0]; v01 += r0[1];
                    v10 += r1[0]; v11 += r1[1];
                }
                float* Cf = (float*)C;
                *(float2*)(Cf + (size_t)row0 * ldc + col) = make_float2(v00, v01);
                *(float2*)(Cf + (size_t)row1 * ldc + col) = make_float2(v10, v11);
            }
        }
    }
}

// ---------------------------------------------------------------------------
// Attention: 128-thread block per (head, b, n), 7 blocks/SM.
//   HMMA score/PV with exact causal truncation; bf16 P overlaid on dead qs;
//   PV split into 12 16x16 tasks, warp w takes {w, w+4, w+8} (balanced 6
//   k-tiles each).  cp.async q/k loads; fp32 accum.
// ---------------------------------------------------------------------------
#define LDQB 36          // uints per qs/ks row: 144B
#define LDP  52          // fp32 score row stride
#define LDPB 56          // bf16 P row stride (elems): 112B  (fits in qs rows)
#define LDVT 56          // vt row stride (elems): 112B

__global__ __launch_bounds__(128, 7)
void attn_kernel(const __nv_bfloat16* __restrict__ qkv, __nv_bfloat16* __restrict__ o)
{
    __shared__ __align__(16) uint32_t qs[TT][LDQB];        // reused as bf16 P
    __shared__ __align__(16) uint32_t ks[TT][LDQB];
    __shared__ __align__(16) __nv_bfloat16 vt[HD][LDVT];   // V^T: [j][s]
    __shared__ __align__(16) float ps[TT][LDP];

    __nv_bfloat16* pb = (__nv_bfloat16*)&qs[0][0];         // [TT][LDPB] overlay

    const int bid = blockIdx.x;
    const int n   = bid % NV;
    const int b   = (bid / NV) % MB;
    const int h   = bid / (NV * MB);
    const int tid = threadIdx.x;

    const size_t brow  = (size_t)(b * TT) * NV + n;
    const size_t qbase = brow * 1536 + h * HD;
    const size_t tq    = (size_t)NV * 1536;

    // ---- load: q/k via cp.async (768 chunks), v via LDG + transpose scatter ----
    for (int idx = tid; idx < 2 * TT * (HD / 8); idx += 128) {
        const int tens = idx / (TT * (HD / 8));      // 0=q, 1=k
        const int c    = idx - tens * (TT * (HD / 8));
        const int t    = c >> 3;
        const int j4   = (c & 7) * 4;
        const __nv_bfloat16* src = qkv + qbase + (size_t)t * tq + tens * 512 + j4 * 2;
        void* dst = (tens == 0) ? (void*)&qs[t][j4] : (void*)&ks[t][j4];
        cp_async16(dst, src);
    }
    cp_commit();
    for (int idx = tid; idx < TT * (HD / 8); idx += 128) {
        const int t  = idx >> 3;
        const int j4 = (idx & 7) * 4;
        const __nv_bfloat16* src = qkv + qbase + (size_t)t * tq + 1024 + j4 * 2;
        uint4 raw = *(const uint4*)src;
        const __nv_bfloat16* e = (const __nv_bfloat16*)&raw;
        const int j8 = j4 * 2;
        #pragma unroll
        for (int q = 0; q < 8; q++) vt[j8 + q][t] = e[q];
    }
    cp_wait0();
    __syncthreads();

    const int w    = tid >> 5;
    const int lane = tid & 31;
    const int lr        = lane & 7;
    const int a_row_off = ((lane >> 3) & 1) * 8;
    const int a_col_off = (lane >> 4) * 8;
    const int b_row_off = (lane >> 4) * 8;
    const int b_col_off = ((lane >> 3) & 1) * 8;
    const int g  = lane >> 2;
    const int t4 = lane & 3;

    const uint32_t qsb = (uint32_t)__cvta_generic_to_shared(&qs[0][0]);
    const uint32_t ksb = (uint32_t)__cvta_generic_to_shared(&ks[0][0]);
    const uint32_t vtb = (uint32_t)__cvta_generic_to_shared(&vt[0][0]);
    const uint32_t pbb = qsb;                                // P overlays qs

    // ---- score: S = Q.K^T via HMMA.  Warp w<3: rows 16w..16w+15, causal-
    //      truncated to column tiles j < 2(w+1).
    if (w < 3) {
        const int i0   = w * 16;
        const int jmax = 2 * (w + 1);
        float c[6][4];
        #pragma unroll
        for (int j = 0; j < 6; j++)
            #pragma unroll
            for (int r = 0; r < 4; r++) c[j][r] = 0.f;

        #pragma unroll
        for (int kk = 0; kk < HD; kk += 16) {
            uint32_t af[4];
            ldsm_x4(af, qsb + (i0 + lr + a_row_off) * 144 + (kk + a_col_off) * 2);
            uint32_t bfr[3][4];
            #pragma unroll
            for (int jp = 0; jp < 3; jp++)
                if (jp < (jmax >> 1))
                    ldsm_x4(bfr[jp], ksb + (jp * 16 + lr + b_row_off) * 144
                                         + (kk + b_col_off) * 2);
            #pragma unroll
            for (int j = 0; j < 6; j++)
                if (j < jmax)
                    mma_bf16(c[j], af, &bfr[j >> 1][(j & 1) * 2]);
        }
        #pragma unroll
        for (int j = 0; j < 6; j++)
            if (j < jmax) {
                const int col = j * 8 + 2 * t4;
                *(float2*)&ps[i0 + g][col]     = make_float2(c[j][0] * 0.125f, c[j][1] * 0.125f);
                *(float2*)&ps[i0 + g + 8][col] = make_float2(c[j][2] * 0.125f, c[j][3] * 0.125f);
            }
    }
    __syncthreads();     // orders: score reads of qs BEFORE pb writes below

    // ---- softmax: warp-per-row (4 warps x 12 rows) -> bf16 P, masked = 0 ----
    {
        #pragma unroll
        for (int r = 0; r < 12; r++) {
            const int i = w * 12 + r;
            float v0 = (lane <= i) ? ps[i][lane] : -1e30f;
            float v1 = (lane + 32 <= i) ? ps[i][lane + 32] : -1e30f;
            float mx = fmaxf(v0, v1);
            #pragma unroll
            for (int off = 16; off; off >>= 1)
                mx = fmaxf(mx, __shfl_xor_sync(0xFFFFFFFFu, mx, off));
            float e0 = (lane <= i)      ? __expf(v0 - mx) : 0.f;
            float e1 = (lane + 32 <= i) ? __expf(v1 - mx) : 0.f;
            float sum = e0 + e1;
            #pragma unroll
            for (int off = 16; off; off >>= 1)
                sum += __shfl_xor_sync(0xFFFFFFFFu, sum, off);
            float inv = 1.f / sum;
            pb[i * LDPB + lane] = __float2bfloat16(e0 * inv);   // masked: exact 0
            if (lane + 32 < TT) pb[i * LDPB + lane + 32] = __float2bfloat16(e1 * inv);
        }
    }
    __syncthreads();

    // ---- PV: O = P.V via HMMA.  12 tasks of 16 rows x 16 cols; warp w does
    //      tasks {w, w+4, w+8} -> causal k-tile weights 1+2+3 = 6 each.
    #pragma unroll
    for (int tsel = 0; tsel < 3; tsel++) {
        const int task = w + tsel * 4;
        const int i0   = (task >> 2) * 16;
        const int c0   = (task & 3) * 16;
        const int kmax = i0 + 16;
        float c[2][4];
        #pragma unroll
        for (int j = 0; j < 2; j++)
            #pragma unroll
            for (int r = 0; r < 4; r++) c[j][r] = 0.f;

        #pragma unroll
        for (int kk = 0; kk < TT; kk += 16)
            if (kk < kmax) {
                uint32_t af[4];
                ldsm_x4(af, pbb + (i0 + lr + a_row_off) * (LDPB * 2) + (kk + a_col_off) * 2);
                uint32_t bfr[4];
                ldsm_x4(bfr, vtb + (c0 + lr + b_row_off) * (LDVT * 2) + (kk + b_col_off) * 2);
                #pragma unroll
                for (int j = 0; j < 2; j++)
                    mma_bf16(c[j], af, &bfr[j * 2]);
            }
        #pragma unroll
        for (int j = 0; j < 2; j++) {
            const int col = c0 + j * 8 + 2 * t4;
            const int r0 = i0 + g, r1 = r0 + 8;
            *(__nv_bfloat162*)(o + (brow + (size_t)r0 * NV) * FF + h * HD + col)
                = __floats2bfloat162_rn(c[j][0], c[j][1]);
            *(__nv_bfloat162*)(o + (brow + (size_t)r1 * NV) * FF + h * HD + col)
                = __floats2bfloat162_rn(c[j][2], c[j][3]);
        }
    }
}

// ---------------------------------------------------------------------------
// LayerNorm over last dim (512). One block (128 threads) per row.
// ---------------------------------------------------------------------------
__global__ __launch_bounds__(128)
void ln_kernel(const float* __restrict__ h, const float* __restrict__ gamma,
               const float* __restrict__ beta, float* __restrict__ out)
{
    __shared__ float red[8];
    const int row = blockIdx.x;
    const int tid = threadIdx.x;

    float4 val = ((const float4*)(h + (size_t)row * FF))[tid];
    float s  = val.x + val.y + val.z + val.w;
    float ss = val.x * val.x + val.y * val.y + val.z * val.z + val.w * val.w;
    #pragma unroll
    for (int off = 16; off; off >>= 1) {
        s  += __shfl_xor_sync(0xFFFFFFFFu, s,  off);
        ss += __shfl_xor_sync(0xFFFFFFFFu, ss, off);
    }
    if ((tid & 31) == 0) { red[tid >> 5] = s; red[4 + (tid >> 5)] = ss; }
    __syncthreads();
    s  = red[0] + red[1] + red[2] + red[3];
    ss = red[4] + red[5] + red[6] + red[7];

    float mean = s * (1.f / 512.f);
    float var  = ss * (1.f / 512.f) - mean * mean;
    float rstd = rsqrtf(var + 1e-5f);

    float4 gm = ((const float4*)gamma)[tid];
    float4 bt = ((const float4*)beta)[tid];
    float4 r;
    r.x = gm.x * (val.x - mean) * rstd + bt.x;
    r.y = gm.y * (val.y - mean) * rstd + bt.y;
    r.z = gm.z * (val.z - mean) * rstd + bt.z;
    r.w = gm.w * (val.w - mean) * rstd + bt.w;
    ((float4*)(out + (size_t)row * FF))[tid] = r;
}

// ---------------------------------------------------------------------------
// Prep kernels
// ---------------------------------------------------------------------------
__global__ void cvt_x_concat(const float* __restrict__ x, __nv_bfloat16* __restrict__ xb,
                             int n4,
                             const float* __restrict__ bq, const float* __restrict__ bk,
                             const float* __restrict__ bv, float* __restrict__ bqkv)
{
    int i = blockIdx.x * blockDim.x + threadIdx.x;
    if (i < n4) {
        float4 v = ((const float4*)x)[i];
        __nv_bfloat162* o = (__nv_bfloat162*)xb + (size_t)i * 2;
        o[0] = __floats2bfloat162_rn(v.x, v.y);
        o[1] = __floats2bfloat162_rn(v.z, v.w);
    }
    if (blockIdx.x == gridDim.x - 1) {
        for (int j = threadIdx.x; j < 1536; j += blockDim.x) {
            float v;
            if (j < 512)       v = bq[j];
            else if (j < 1024) v = bk[j - 512];
            else               v = bv[j - 1024];
            bqkv[j] = v;
        }
    }
}

__global__ void transp_set(const float* __restrict__ Wa, const float* __restrict__ Wb,
                           const float* __restrict__ Wc,
                           __nv_bfloat16* __restrict__ Ta,
                           __nv_bfloat16* __restrict__ Tb,
                           __nv_bfloat16* __restrict__ Tc)
{
    __shared__ float t[32][33];
    const float* W = (blockIdx.z == 0) ? Wa : (blockIdx.z == 1) ? Wb : Wc;
    __nv_bfloat16* Wt = (blockIdx.z == 0) ? Ta : (blockIdx.z == 1) ? Tb : Tc;
    if (W == nullptr) return;
    int bx = blockIdx.x * 32, by = blockIdx.y * 32;
    int tx = threadIdx.x, ty = threadIdx.y;
    #pragma unroll
    for (int r = 0; r < 32; r += 8)
        t[ty + r][tx] = W[(size_t)(by + ty + r) * 512 + bx + tx];
    __syncthreads();
    #pragma unroll
    for (int r = 0; r < 32; r += 8)
        Wt[(size_t)(bx + ty + r) * 512 + by + tx] = __float2bfloat16(t[tx][ty + r]);
}

// ---------------------------------------------------------------------------
// Launch
// ---------------------------------------------------------------------------
extern "C" void kernel_launch(void* const* d_in, const int* in_sizes, int n_in,
                              void* d_out, int out_size)
{
    const float* x     = (const float*)d_in[0];
    const float* Wq    = (const float*)d_in[1];
    const float* bq    = (const float*)d_in[2];
    const float* Wk    = (const float*)d_in[3];
    const float* bk    = (const float*)d_in[4];
    const float* Wv    = (const float*)d_in[5];
    const float* bv    = (const float*)d_in[6];
    const float* W1    = (const float*)d_in[7];
    const float* b1    = (const float*)d_in[8];
    const float* W2    = (const float*)d_in[9];
    const float* b2    = (const float*)d_in[10];
    const float* gamma = (const float*)d_in[11];
    const float* beta  = (const float*)d_in[12];
    float* out = (float*)d_out;

    float* s;
    cudaGetSymbolAddress((void**)&s, g_scratch);
    __nv_bfloat16*  qkvb  = (__nv_bfloat16*)s;                     // [M,1536] bf16
    float*          h2    = s + 3 * SZ;                            // [M,512]  fp32
    __nv_bfloat16*  xb    = (__nv_bfloat16*)(s + 4 * SZ);          // [M,512]  bf16
    __nv_bfloat16*  ob    = (__nv_bfloat16*)(s + 4 * SZ + SZ / 2); // [M,512]  bf16
    __nv_bfloat16*  h1b   = (__nv_bfloat16*)(s + 5 * SZ);          // [M,512]  bf16
    __nv_bfloat16*  wqkvT = (__nv_bfloat16*)(s + 5 * SZ + SZ / 2); // [1536,512] bf16
    __nv_bfloat16*  w1T   = wqkvT + (size_t)1536 * 512;
    __nv_bfloat16*  w2T   = w1T   + (size_t)512 * 512;
    float*          bqkv  = (float*)(w2T + (size_t)512 * 512);     // [1536]

    cudaFuncSetAttribute(gemm_bf16, cudaFuncAttributeMaxDynamicSharedMemorySize, GEMM_SMEM);

    // prep (2 launches before QKV)
    cvt_x_concat<<<(int)((SZ / 4 + 255) / 256), 256>>>(
        x, xb, (int)(SZ / 4), bq, bk, bv, bqkv);
    transp_set<<<dim3(16, 16, 3), dim3(32, 8)>>>(
        Wq, Wk, Wv,
        wqkvT, wqkvT + (size_t)512 * 512, wqkvT + (size_t)1024 * 512);

    // fused QKV GEMM -> bf16 qkv
    gemm_bf16<<<dim3(1536 / BN, MROWS / BM), 128, GEMM_SMEM>>>(
        xb, wqkvT, bqkv, nullptr, qkvb, 1536, 3);

    attn_kernel<<<NHEAD * MB * NV, 128>>>(qkvb, ob);

    // W1/W2 transpose deferred (only needed by FFN1/FFN2)
    transp_set<<<dim3(16, 16, 2), dim3(32, 8)>>>(
        W1, W2, nullptr, w1T, w2T, nullptr);

    // FFN1 (+GELU -> bf16)
    gemm_bf16<<<dim3(FF / BN, MROWS / BM), 128, GEMM_SMEM>>>(
        ob, w1T, b1, nullptr, h1b, FF, 1);
    // FFN2 (+bias +residual -> fp32)
    gemm_bf16<<<dim3(FF / BN, MROWS / BM), 128, GEMM_SMEM>>>(
        h1b, w2T, b2, x, h2, FF, 2);

    ln_kernel<<<MROWS, 128>>>(h2, gamma, beta, out);
}